// round 7
// baseline (speedup 1.0000x reference)
#include <cuda_runtime.h>
#include <cstdint>
#include <math.h>

#define BB 4
#define SS 2048
#define DD 768
#define HH 12
#define DKK 64

typedef unsigned long long ull;

static const long long OUT_ELEMS  = (long long)BB * SS * DD;
static const long long ATTN_ELEMS = (long long)BB * HH * SS * SS;

// Scratch
__device__ float g_q[BB * HH * SS * DKK];
__device__ float g_k[BB * HH * SS * DKK];
__device__ float g_v[BB * HH * SS * DKK];
__device__ float g_ctx[BB * SS * DD];
__device__ float g_pre[BB * SS * DD];
__device__ float g_psum[(size_t)BB * HH * SS * 2];
__device__ float g_rowinv[(size_t)BB * HH * SS];
__device__ uint32_t g_maskbits[(size_t)BB * SS * (SS / 32)];  // 2 MB

__device__ __forceinline__ uint32_t cvt_tf32(float x) {
    uint32_t u; asm("cvt.rna.tf32.f32 %0, %1;" : "=r"(u) : "f"(x)); return u;
}

__device__ __forceinline__ void mma8(float* c, const uint32_t* a, const uint32_t* b) {
    asm("mma.sync.aligned.m16n8k8.row.col.f32.tf32.tf32.f32 "
        "{%0,%1,%2,%3},{%4,%5,%6,%7},{%8,%9},{%0,%1,%2,%3};"
        : "+f"(c[0]), "+f"(c[1]), "+f"(c[2]), "+f"(c[3])
        : "r"(a[0]), "r"(a[1]), "r"(a[2]), "r"(a[3]), "r"(b[0]), "r"(b[1]));
}

__device__ __forceinline__ void cp16(uint32_t dst, const void* src) {
    asm volatile("cp.async.cg.shared.global [%0], [%1], 16;" :: "r"(dst), "l"(src));
}
__device__ __forceinline__ void cp_commit() { asm volatile("cp.async.commit_group;"); }
template<int N> __device__ __forceinline__ void cp_wait() {
    asm volatile("cp.async.wait_group %0;" :: "n"(N));
}

// ---------------------------------------------------------------------------
// Mask bit-pack: int32 [4,2048,2048] -> bitmask. bit=1 -> masked.
// ---------------------------------------------------------------------------
__global__ void __launch_bounds__(256) maskpack_kernel(const int* __restrict__ pad)
{
    size_t w = (size_t)blockIdx.x * 256 + threadIdx.x;
    const int4* p = reinterpret_cast<const int4*>(pad + w * 32);
    uint32_t bits = 0;
    #pragma unroll
    for (int t = 0; t < 8; t++) {
        int4 v = p[t];
        bits |= (uint32_t)(v.x != 0) << (4 * t);
        bits |= (uint32_t)(v.y != 0) << (4 * t + 1);
        bits |= (uint32_t)(v.z != 0) << (4 * t + 2);
        bits |= (uint32_t)(v.w != 0) << (4 * t + 3);
    }
    g_maskbits[w] = bits;
}

// ---------------------------------------------------------------------------
// QKV projection (merged): Y = X @ W + bias, [B,H,S,DK] layout.
// cp.async double-buffered, tf32 MMA. Block 128x64, warps 2x2 of 32x32.
// ---------------------------------------------------------------------------
__global__ void __launch_bounds__(256) qkv_kernel(
    const float* __restrict__ Q, const float* __restrict__ K, const float* __restrict__ V,
    const float* __restrict__ Wq, const float* __restrict__ Wk, const float* __restrict__ Wv,
    const float* __restrict__ bq, const float* __restrict__ bk, const float* __restrict__ bv)
{
    const int z = blockIdx.z;
    const float* X = (z == 0) ? Q : (z == 1) ? K : V;
    const float* W = (z == 0) ? Wq : (z == 1) ? Wk : Wv;
    const float* bias = (z == 0) ? bq : (z == 1) ? bk : bv;
    float* Y = (z == 0) ? g_q : (z == 1) ? g_k : g_v;

    extern __shared__ float smf[];
    const uint32_t smb = (uint32_t)__cvta_generic_to_shared(smf);

    const int tid = threadIdx.x, wid = tid >> 5, lane = tid & 31;
    const int gid = lane >> 2, tig = lane & 3;
    const int m0 = blockIdx.y * 128, n0 = blockIdx.x * 64;
    const int wm = (wid >> 1) * 32, wn = (wid & 1) * 32;

    float acc[2][4][4] = {};

    #define XS(s,r,c) smf[(s)*8704 + (r)*68 + (c)]
    #define WS(s,r,c) smf[17408 + (s)*4352 + (r)*68 + (c)]
    auto load_chunk = [&](int s, int k0) {
        #pragma unroll
        for (int t = 0; t < 8; t++) {
            int e = (tid + t * 256) * 4, r = e >> 6, c = e & 63;
            cp16(smb + (uint32_t)((s * 8704 + r * 68 + c) * 4),
                 X + (size_t)(m0 + r) * DD + k0 + c);
        }
        #pragma unroll
        for (int t = 0; t < 4; t++) {
            int e = (tid + t * 256) * 4, r = e >> 6, c = e & 63;
            cp16(smb + (uint32_t)((17408 + s * 4352 + r * 68 + c) * 4),
                 W + (size_t)(k0 + r) * DD + n0 + c);
        }
        cp_commit();
    };

    load_chunk(0, 0);
    for (int it = 0; it < 12; it++) {
        if (it + 1 < 12) { load_chunk((it + 1) & 1, (it + 1) * 64); cp_wait<1>(); }
        else cp_wait<0>();
        __syncthreads();
        const int s = it & 1;
        #pragma unroll
        for (int kk = 0; kk < 64; kk += 8) {
            uint32_t a[2][4], b[4][2];
            #pragma unroll
            for (int mi = 0; mi < 2; mi++) {
                int r = wm + mi * 16 + gid;
                a[mi][0] = cvt_tf32(XS(s, r, kk + tig));
                a[mi][1] = cvt_tf32(XS(s, r + 8, kk + tig));
                a[mi][2] = cvt_tf32(XS(s, r, kk + tig + 4));
                a[mi][3] = cvt_tf32(XS(s, r + 8, kk + tig + 4));
            }
            #pragma unroll
            for (int nj = 0; nj < 4; nj++) {
                int n = wn + nj * 8 + gid;
                b[nj][0] = cvt_tf32(WS(s, kk + tig, n));
                b[nj][1] = cvt_tf32(WS(s, kk + tig + 4, n));
            }
            #pragma unroll
            for (int mi = 0; mi < 2; mi++)
                #pragma unroll
                for (int nj = 0; nj < 4; nj++) mma8(acc[mi][nj], a[mi], b[nj]);
        }
        __syncthreads();
    }
    #undef XS
    #undef WS

    #pragma unroll
    for (int mi = 0; mi < 2; mi++)
        #pragma unroll
        for (int rr = 0; rr < 2; rr++) {
            int r = m0 + wm + mi * 16 + gid + rr * 8;
            #pragma unroll
            for (int nj = 0; nj < 4; nj++) {
                int c = n0 + wn + nj * 8 + tig * 2;
                float v0 = acc[mi][nj][rr * 2 + 0] + bias[c];
                float v1 = acc[mi][nj][rr * 2 + 1] + bias[c + 1];
                int b_ = r / SS, sidx = r % SS, h = c / DKK, d = c % DKK;
                *reinterpret_cast<float2*>(&Y[(((size_t)b_ * HH + h) * SS + sidx) * DKK + d]) =
                    make_float2(v0, v1);
            }
        }
}

// ---------------------------------------------------------------------------
// Fused scores+exp+context (flash-style, no attn materialization).
// Per (bh, qtile 128): loop k-chunks of 64: QK^T MMA -> exp (masked) ->
// rowsum accum + P->smem -> P@V MMA accumulate. Writes raw ctx + 2 psums/row.
// smem floats: Qs@0[128][68], Ps@8704[128][68](u32 tf32),
//              Ks@17408+s*4352[64][68], Vs@26112+s*4352[64][68].
// ---------------------------------------------------------------------------
__global__ void __launch_bounds__(256) scorectx_kernel()
{
    extern __shared__ float smf[];
    uint32_t* smu = reinterpret_cast<uint32_t*>(smf);
    const uint32_t smb = (uint32_t)__cvta_generic_to_shared(smf);

    const int bh = blockIdx.y, b_ = bh / HH;
    const int q0 = blockIdx.x * 128;
    const int tid = threadIdx.x, wid = tid >> 5, lane = tid & 31;
    const int gid = lane >> 2, tig = lane & 3;
    const int wm = (wid >> 1) * 32, wn = (wid & 1) * 32;

    const float* qp = g_q + ((size_t)bh * SS + q0) * DKK;
    const float* kp = g_k + (size_t)bh * SS * DKK;
    const float* vp = g_v + (size_t)bh * SS * DKK;

    #define QS(r,c)   smu[(r)*68 + (c)]
    #define PS(r,c)   smu[8704 + (r)*68 + (c)]
    #define KS(s,r,c) smf[17408 + (s)*4352 + (r)*68 + (c)]
    #define VS(s,r,c) smf[26112 + (s)*4352 + (r)*68 + (c)]

    // Q tile: load + convert once
    #pragma unroll
    for (int t = 0; t < 8; t++) {
        int e = (tid + t * 256) * 4, r = e >> 6, c = e & 63;
        float4 v = *reinterpret_cast<const float4*>(qp + (size_t)r * DKK + c);
        QS(r, c) = cvt_tf32(v.x); QS(r, c + 1) = cvt_tf32(v.y);
        QS(r, c + 2) = cvt_tf32(v.z); QS(r, c + 3) = cvt_tf32(v.w);
    }

    auto load_kv = [&](int s, int k0) {
        #pragma unroll
        for (int t = 0; t < 4; t++) {
            int e = (tid + t * 256) * 4, r = e >> 6, c = e & 63;
            cp16(smb + (uint32_t)((17408 + s * 4352 + r * 68 + c) * 4),
                 kp + (size_t)(k0 + r) * DKK + c);
            cp16(smb + (uint32_t)((26112 + s * 4352 + r * 68 + c) * 4),
                 vp + (size_t)(k0 + r) * DKK + c);
        }
        cp_commit();
    };

    float acc_o[2][4][4] = {};
    float rsum[2][2] = {};

    load_kv(0, 0);
    for (int it = 0; it < 32; it++) {
        if (it + 1 < 32) { load_kv((it + 1) & 1, (it + 1) * 64); cp_wait<1>(); }
        else cp_wait<0>();
        __syncthreads();
        const int s = it & 1;
        const int k0 = it * 64;

        // in-place tf32 convert K,V for this stage
        #pragma unroll
        for (int t = 0; t < 4; t++) {
            int e = (tid + t * 256) * 4, r = e >> 6, c = e & 63;
            uint32_t* ku = reinterpret_cast<uint32_t*>(&KS(s, r, c));
            float4 kv = *reinterpret_cast<const float4*>(&KS(s, r, c));
            ku[0] = cvt_tf32(kv.x); ku[1] = cvt_tf32(kv.y);
            ku[2] = cvt_tf32(kv.z); ku[3] = cvt_tf32(kv.w);
            uint32_t* vu = reinterpret_cast<uint32_t*>(&VS(s, r, c));
            float4 vv = *reinterpret_cast<const float4*>(&VS(s, r, c));
            vu[0] = cvt_tf32(vv.x); vu[1] = cvt_tf32(vv.y);
            vu[2] = cvt_tf32(vv.z); vu[3] = cvt_tf32(vv.w);
        }
        __syncthreads();

        // QK^T: M=128 q, N=64 k-cols, K=64 dk
        float acc_s[2][4][4] = {};
        #pragma unroll
        for (int kk = 0; kk < 64; kk += 8) {
            uint32_t a[2][4], b[4][2];
            #pragma unroll
            for (int mi = 0; mi < 2; mi++) {
                int r = wm + mi * 16 + gid;
                a[mi][0] = QS(r, kk + tig);     a[mi][1] = QS(r + 8, kk + tig);
                a[mi][2] = QS(r, kk + tig + 4); a[mi][3] = QS(r + 8, kk + tig + 4);
            }
            #pragma unroll
            for (int nj = 0; nj < 4; nj++) {
                int n = wn + nj * 8 + gid;
                b[nj][0] = __float_as_uint(KS(s, n, kk + tig));
                b[nj][1] = __float_as_uint(KS(s, n, kk + tig + 4));
            }
            #pragma unroll
            for (int mi = 0; mi < 2; mi++)
                #pragma unroll
                for (int nj = 0; nj < 4; nj++) mma8(acc_s[mi][nj], a[mi], b[nj]);
        }

        // exp + mask -> Ps (tf32 bits) + rowsum
        #pragma unroll
        for (int mi = 0; mi < 2; mi++)
            #pragma unroll
            for (int rr = 0; rr < 2; rr++) {
                int qrl = wm + mi * 16 + gid + rr * 8;
                uint32_t mw = g_maskbits[((size_t)b_ * SS + q0 + qrl) * (SS / 32)
                                         + ((k0 + wn) >> 5)];
                #pragma unroll
                for (int nj = 0; nj < 4; nj++) {
                    int j = nj * 8 + tig * 2;
                    float v0 = acc_s[mi][nj][rr * 2 + 0] * 0.125f;
                    float v1 = acc_s[mi][nj][rr * 2 + 1] * 0.125f;
                    float p0 = ((mw >> j) & 1u) ? 0.f : __expf(v0);
                    float p1 = ((mw >> (j + 1)) & 1u) ? 0.f : __expf(v1);
                    rsum[mi][rr] += p0 + p1;
                    PS(qrl, wn + j)     = cvt_tf32(p0);
                    PS(qrl, wn + j + 1) = cvt_tf32(p1);
                }
            }
        __syncthreads();   // Ps complete

        // P @ V: M=128 q, N=64 dv, K=64 k-local
        #pragma unroll
        for (int kk = 0; kk < 64; kk += 8) {
            uint32_t a[2][4], b[4][2];
            #pragma unroll
            for (int mi = 0; mi < 2; mi++) {
                int r = wm + mi * 16 + gid;
                a[mi][0] = PS(r, kk + tig);     a[mi][1] = PS(r + 8, kk + tig);
                a[mi][2] = PS(r, kk + tig + 4); a[mi][3] = PS(r + 8, kk + tig + 4);
            }
            #pragma unroll
            for (int nj = 0; nj < 4; nj++) {
                int n = wn + nj * 8 + gid;
                b[nj][0] = __float_as_uint(VS(s, kk + tig, n));
                b[nj][1] = __float_as_uint(VS(s, kk + tig + 4, n));
            }
            #pragma unroll
            for (int mi = 0; mi < 2; mi++)
                #pragma unroll
                for (int nj = 0; nj < 4; nj++) mma8(acc_o[mi][nj], a[mi], b[nj]);
        }
        __syncthreads();   // done with Ps & this KV stage
    }
    #undef QS
    #undef PS
    #undef KS
    #undef VS

    // psum: reduce over tig, 2 partials per row (one per n-warp)
    #pragma unroll
    for (int mi = 0; mi < 2; mi++)
        #pragma unroll
        for (int rr = 0; rr < 2; rr++) {
            float rs = rsum[mi][rr];
            rs += __shfl_xor_sync(~0u, rs, 1);
            rs += __shfl_xor_sync(~0u, rs, 2);
            if (tig == 0) {
                int qr = q0 + wm + mi * 16 + gid + rr * 8;
                g_psum[((size_t)bh * SS + qr) * 2 + (wid & 1)] = rs;
            }
        }

    // raw (unnormalized) ctx -> [B,S,H*DV]
    const int hb = bh % HH;
    #pragma unroll
    for (int mi = 0; mi < 2; mi++)
        #pragma unroll
        for (int rr = 0; rr < 2; rr++) {
            int s = q0 + wm + mi * 16 + gid + rr * 8;
            #pragma unroll
            for (int nj = 0; nj < 4; nj++) {
                int d = wn + nj * 8 + tig * 2;
                *reinterpret_cast<float2*>(&g_ctx[((size_t)b_ * SS + s) * DD + hb * DKK + d]) =
                    make_float2(acc_o[mi][nj][rr * 2], acc_o[mi][nj][rr * 2 + 1]);
            }
        }
}

// ---------------------------------------------------------------------------
// Row-sum reduce -> 1/sum (2 partials per row).
// ---------------------------------------------------------------------------
__global__ void __launch_bounds__(256) rowinv_kernel()
{
    size_t idx = (size_t)blockIdx.x * 256 + threadIdx.x;
    float2 p = *reinterpret_cast<const float2*>(g_psum + idx * 2);
    g_rowinv[idx] = 1.0f / (p.x + p.y);
}

// ---------------------------------------------------------------------------
// Normalize ctx in place: g_ctx[b,s,h*64+d] *= rowinv[b,h,s].
// ---------------------------------------------------------------------------
__global__ void __launch_bounds__(256) ctxnorm_kernel()
{
    size_t i4 = (size_t)blockIdx.x * 256 + threadIdx.x;
    size_t f = i4 * 4;
    int r = (int)(f / DD), c = (int)(f % DD);
    int b = r / SS, s = r % SS, h = c >> 6;
    float inv = g_rowinv[((size_t)b * HH + h) * SS + s];
    float4* p = reinterpret_cast<float4*>(g_ctx) + i4;
    float4 v = *p;
    v.x *= inv; v.y *= inv; v.z *= inv; v.w *= inv;
    *p = v;
}

// ---------------------------------------------------------------------------
// Attn writeback: recompute QK^T, exp*inv, write final attn (coalesced).
// smem u32: Qs@0[128][68], Ks@8704[128][68], invs@17408[128]; Ss overlays @0.
// ---------------------------------------------------------------------------
__global__ void __launch_bounds__(256) attnwrite_kernel(float* __restrict__ attn)
{
    extern __shared__ uint32_t smu[];
    uint32_t (*Qs)[68] = reinterpret_cast<uint32_t(*)[68]>(smu);
    uint32_t (*Ks)[68] = reinterpret_cast<uint32_t(*)[68]>(smu + 128 * 68);
    float* invs = reinterpret_cast<float*>(smu + 17408);
    float (*Ss)[132] = reinterpret_cast<float(*)[132]>(smu);

    const int bh = blockIdx.z, b_ = bh / HH;
    const int q0 = blockIdx.y * 128, k0 = blockIdx.x * 128;
    const int tid = threadIdx.x, wid = tid >> 5, lane = tid & 31;
    const int gid = lane >> 2, tig = lane & 3;
    const int wm = (wid >> 1) * 32, wn = (wid & 1) * 64;

    const float* qp = g_q + ((size_t)bh * SS + q0) * DKK;
    const float* kp = g_k + ((size_t)bh * SS + k0) * DKK;

    if (tid < 128) invs[tid] = g_rowinv[(size_t)bh * SS + q0 + tid];
    #pragma unroll
    for (int t = 0; t < 8; t++) {
        int e = (tid + t * 256) * 4, r = e >> 6, c = e & 63;
        float4 v = *reinterpret_cast<const float4*>(qp + (size_t)r * DKK + c);
        Qs[r][c] = cvt_tf32(v.x); Qs[r][c+1] = cvt_tf32(v.y);
        Qs[r][c+2] = cvt_tf32(v.z); Qs[r][c+3] = cvt_tf32(v.w);
        float4 w = *reinterpret_cast<const float4*>(kp + (size_t)r * DKK + c);
        Ks[r][c] = cvt_tf32(w.x); Ks[r][c+1] = cvt_tf32(w.y);
        Ks[r][c+2] = cvt_tf32(w.z); Ks[r][c+3] = cvt_tf32(w.w);
    }
    __syncthreads();

    float acc[2][8][4] = {};
    #pragma unroll
    for (int kk = 0; kk < 64; kk += 8) {
        uint32_t a[2][4], b[8][2];
        #pragma unroll
        for (int mi = 0; mi < 2; mi++) {
            int r = wm + mi * 16 + gid;
            a[mi][0] = Qs[r][kk + tig];     a[mi][1] = Qs[r + 8][kk + tig];
            a[mi][2] = Qs[r][kk + tig + 4]; a[mi][3] = Qs[r + 8][kk + tig + 4];
        }
        #pragma unroll
        for (int nj = 0; nj < 8; nj++) {
            int n = wn + nj * 8 + gid;
            b[nj][0] = Ks[n][kk + tig]; b[nj][1] = Ks[n][kk + tig + 4];
        }
        #pragma unroll
        for (int mi = 0; mi < 2; mi++)
            #pragma unroll
            for (int nj = 0; nj < 8; nj++) mma8(acc[mi][nj], a[mi], b[nj]);
    }
    __syncthreads();   // Qs/Ks reads done before Ss overwrite

    #pragma unroll
    for (int mi = 0; mi < 2; mi++)
        #pragma unroll
        for (int rr = 0; rr < 2; rr++) {
            int qrl = wm + mi * 16 + gid + rr * 8;
            int qr = q0 + qrl;
            float inv = invs[qrl];
            uint2 mw = *reinterpret_cast<const uint2*>(
                g_maskbits + ((size_t)b_ * SS + qr) * (SS / 32) + (k0 + wn) / 32);
            ull m64 = (ull)mw.x | ((ull)mw.y << 32);
            #pragma unroll
            for (int nj = 0; nj < 8; nj++) {
                int j = nj * 8 + tig * 2;
                float v0 = acc[mi][nj][rr * 2 + 0] * 0.125f;
                float v1 = acc[mi][nj][rr * 2 + 1] * 0.125f;
                float p0 = ((m64 >> j) & 1ull) ? 0.f : __expf(v0) * inv;
                float p1 = ((m64 >> (j + 1)) & 1ull) ? 0.f : __expf(v1) * inv;
                *reinterpret_cast<float2*>(&Ss[qrl][wn + j]) = make_float2(p0, p1);
            }
        }
    __syncthreads();

    const size_t base = (size_t)bh * SS * SS;
    #pragma unroll
    for (int t = 0; t < 16; t++) {
        int idx = tid + t * 256;
        int r = idx >> 5, c4 = (idx & 31) * 4;
        float4 v = *reinterpret_cast<const float4*>(&Ss[r][c4]);
        *reinterpret_cast<float4*>(attn + base + (size_t)(q0 + r) * SS + k0 + c4) = v;
    }
}

// ---------------------------------------------------------------------------
// Output projection: g_pre = g_ctx @ Wo + bo + resid.
// ---------------------------------------------------------------------------
__global__ void __launch_bounds__(256) outproj_kernel(
    const float* __restrict__ W, const float* __restrict__ bias,
    const float* __restrict__ resid)
{
    const float* X = g_ctx;
    extern __shared__ float smf[];
    const uint32_t smb = (uint32_t)__cvta_generic_to_shared(smf);

    const int tid = threadIdx.x, wid = tid >> 5, lane = tid & 31;
    const int gid = lane >> 2, tig = lane & 3;
    const int m0 = blockIdx.y * 128, n0 = blockIdx.x * 64;
    const int wm = (wid >> 1) * 32, wn = (wid & 1) * 32;

    float acc[2][4][4] = {};

    #define XS(s,r,c) smf[(s)*8704 + (r)*68 + (c)]
    #define WS(s,r,c) smf[17408 + (s)*4352 + (r)*68 + (c)]
    auto load_chunk = [&](int s, int k0) {
        #pragma unroll
        for (int t = 0; t < 8; t++) {
            int e = (tid + t * 256) * 4, r = e >> 6, c = e & 63;
            cp16(smb + (uint32_t)((s * 8704 + r * 68 + c) * 4),
                 X + (size_t)(m0 + r) * DD + k0 + c);
        }
        #pragma unroll
        for (int t = 0; t < 4; t++) {
            int e = (tid + t * 256) * 4, r = e >> 6, c = e & 63;
            cp16(smb + (uint32_t)((17408 + s * 4352 + r * 68 + c) * 4),
                 W + (size_t)(k0 + r) * DD + n0 + c);
        }
        cp_commit();
    };

    load_chunk(0, 0);
    for (int it = 0; it < 12; it++) {
        if (it + 1 < 12) { load_chunk((it + 1) & 1, (it + 1) * 64); cp_wait<1>(); }
        else cp_wait<0>();
        __syncthreads();
        const int s = it & 1;
        #pragma unroll
        for (int kk = 0; kk < 64; kk += 8) {
            uint32_t a[2][4], b[4][2];
            #pragma unroll
            for (int mi = 0; mi < 2; mi++) {
                int r = wm + mi * 16 + gid;
                a[mi][0] = cvt_tf32(XS(s, r, kk + tig));
                a[mi][1] = cvt_tf32(XS(s, r + 8, kk + tig));
                a[mi][2] = cvt_tf32(XS(s, r, kk + tig + 4));
                a[mi][3] = cvt_tf32(XS(s, r + 8, kk + tig + 4));
            }
            #pragma unroll
            for (int nj = 0; nj < 4; nj++) {
                int n = wn + nj * 8 + gid;
                b[nj][0] = cvt_tf32(WS(s, kk + tig, n));
                b[nj][1] = cvt_tf32(WS(s, kk + tig + 4, n));
            }
            #pragma unroll
            for (int mi = 0; mi < 2; mi++)
                #pragma unroll
                for (int nj = 0; nj < 4; nj++) mma8(acc[mi][nj], a[mi], b[nj]);
        }
        __syncthreads();
    }
    #undef XS
    #undef WS

    #pragma unroll
    for (int mi = 0; mi < 2; mi++)
        #pragma unroll
        for (int rr = 0; rr < 2; rr++) {
            int r = m0 + wm + mi * 16 + gid + rr * 8;
            #pragma unroll
            for (int nj = 0; nj < 4; nj++) {
                int c = n0 + wn + nj * 8 + tig * 2;
                float v0 = acc[mi][nj][rr * 2 + 0] + bias[c];
                float v1 = acc[mi][nj][rr * 2 + 1] + bias[c + 1];
                const float2 rs = *reinterpret_cast<const float2*>(&resid[(size_t)r * DD + c]);
                *reinterpret_cast<float2*>(&g_pre[(size_t)r * DD + c]) =
                    make_float2(v0 + rs.x, v1 + rs.y);
            }
        }
}

// ---------------------------------------------------------------------------
// LayerNorm over D=768.
// ---------------------------------------------------------------------------
__global__ void __launch_bounds__(256) ln_kernel(
    const float* __restrict__ lg, const float* __restrict__ lb, float* __restrict__ out)
{
    const size_t row = blockIdx.x;
    const float* x = g_pre + row * DD;
    const int tid = threadIdx.x;
    __shared__ float red[8];

    float v[3];
    float s = 0.f;
    #pragma unroll
    for (int t = 0; t < 3; t++) { v[t] = x[tid + t * 256]; s += v[t]; }
    #pragma unroll
    for (int o = 16; o; o >>= 1) s += __shfl_xor_sync(~0u, s, o);
    if ((tid & 31) == 0) red[tid >> 5] = s;
    __syncthreads();
    s = 0.f;
    #pragma unroll
    for (int w = 0; w < 8; w++) s += red[w];
    const float mu = s * (1.0f / DD);
    __syncthreads();

    float var = 0.f;
    #pragma unroll
    for (int t = 0; t < 3; t++) { float d = v[t] - mu; var += d * d; }
    #pragma unroll
    for (int o = 16; o; o >>= 1) var += __shfl_xor_sync(~0u, var, o);
    if ((tid & 31) == 0) red[tid >> 5] = var;
    __syncthreads();
    var = 0.f;
    #pragma unroll
    for (int w = 0; w < 8; w++) var += red[w];
    const float inv = rsqrtf(var * (1.0f / DD) + 1e-5f);

    #pragma unroll
    for (int t = 0; t < 3; t++) {
        int c = tid + t * 256;
        out[row * DD + c] = (v[t] - mu) * inv * lg[c] + lb[c];
    }
}

// ---------------------------------------------------------------------------
extern "C" void kernel_launch(void* const* d_in, const int* in_sizes, int n_in,
                              void* d_out, int out_size)
{
    const float* Q  = (const float*)d_in[0];
    const float* K  = (const float*)d_in[1];
    const float* V  = (const float*)d_in[2];
    const int*   pad = (const int*)d_in[3];
    const float* Wq = (const float*)d_in[4];
    const float* bq = (const float*)d_in[5];
    const float* Wk = (const float*)d_in[6];
    const float* bk = (const float*)d_in[7];
    const float* Wv = (const float*)d_in[8];
    const float* bv = (const float*)d_in[9];
    const float* Wo = (const float*)d_in[10];
    const float* bo = (const float*)d_in[11];
    const float* lg = (const float*)d_in[12];
    const float* lb = (const float*)d_in[13];
    float* out = (float*)d_out;

    float* attn = ((long long)out_size >= OUT_ELEMS + ATTN_ELEMS) ? (out + OUT_ELEMS)
                                                                  : nullptr;

    const int GEMM_SMEM = 26112 * 4;   // 104448
    const int SC_SMEM   = 34816 * 4;   // 139264
    const int AW_SMEM   = 17536 * 4;   // 70144
    cudaFuncSetAttribute(qkv_kernel, cudaFuncAttributeMaxDynamicSharedMemorySize, GEMM_SMEM);
    cudaFuncSetAttribute(outproj_kernel, cudaFuncAttributeMaxDynamicSharedMemorySize, GEMM_SMEM);
    cudaFuncSetAttribute(scorectx_kernel, cudaFuncAttributeMaxDynamicSharedMemorySize, SC_SMEM);
    cudaFuncSetAttribute(attnwrite_kernel, cudaFuncAttributeMaxDynamicSharedMemorySize, AW_SMEM);

    maskpack_kernel<<<(BB * SS * (SS / 32)) / 256, 256>>>(pad);

    dim3 gq(DD / 64, (BB * SS) / 128, 3);       // (12, 64, 3)
    qkv_kernel<<<gq, 256, GEMM_SMEM>>>(Q, K, V, Wq, Wk, Wv, bq, bk, bv);

    dim3 gsc(SS / 128, BB * HH);                // (16, 48)
    scorectx_kernel<<<gsc, 256, SC_SMEM>>>();

    rowinv_kernel<<<(BB * HH * SS) / 256, 256>>>();

    ctxnorm_kernel<<<(BB * SS * DD / 4) / 256, 256>>>();

    if (attn) {
        dim3 gaw(SS / 128, SS / 128, BB * HH);  // (16, 16, 48)
        attnwrite_kernel<<<gaw, 256, AW_SMEM>>>(attn);
    }

    dim3 gp(DD / 64, (BB * SS) / 128);          // (12, 64)
    outproj_kernel<<<gp, 256, GEMM_SMEM>>>(Wo, bo, Q);

    ln_kernel<<<BB * SS, 256>>>(lg, lb, out);
}

// round 8
// speedup vs baseline: 1.1320x; 1.1320x over previous
#include <cuda_runtime.h>
#include <cstdint>
#include <math.h>

#define BB 4
#define SS 2048
#define DD 768
#define HH 12
#define DKK 64

typedef unsigned long long ull;

static const long long OUT_ELEMS  = (long long)BB * SS * DD;
static const long long ATTN_ELEMS = (long long)BB * HH * SS * SS;

// Scratch
__device__ float g_q[BB * HH * SS * DKK];
__device__ float g_k[BB * HH * SS * DKK];
__device__ float g_v[BB * HH * SS * DKK];
__device__ float g_ctx[BB * SS * DD];
__device__ float g_pre[BB * SS * DD];
__device__ float g_psum[(size_t)BB * HH * SS * 32];
__device__ float g_rowinv[(size_t)BB * HH * SS];
__device__ uint32_t g_maskbits[(size_t)BB * SS * (SS / 32)];  // 2 MB
__device__ float g_attn_fb[(long long)BB * HH * SS * SS];

__device__ __forceinline__ uint32_t cvt_tf32(float x) {
    uint32_t u; asm("cvt.rna.tf32.f32 %0, %1;" : "=r"(u) : "f"(x)); return u;
}

__device__ __forceinline__ void mma8(float* c, const uint32_t* a, const uint32_t* b) {
    asm("mma.sync.aligned.m16n8k8.row.col.f32.tf32.tf32.f32 "
        "{%0,%1,%2,%3},{%4,%5,%6,%7},{%8,%9},{%0,%1,%2,%3};"
        : "+f"(c[0]), "+f"(c[1]), "+f"(c[2]), "+f"(c[3])
        : "r"(a[0]), "r"(a[1]), "r"(a[2]), "r"(a[3]), "r"(b[0]), "r"(b[1]));
}

__device__ __forceinline__ void cp16(uint32_t dst, const void* src) {
    asm volatile("cp.async.cg.shared.global [%0], [%1], 16;" :: "r"(dst), "l"(src));
}
__device__ __forceinline__ void cp_commit() { asm volatile("cp.async.commit_group;"); }
template<int N> __device__ __forceinline__ void cp_wait() {
    asm volatile("cp.async.wait_group %0;" :: "n"(N));
}

// ---------------------------------------------------------------------------
// Mask bit-pack: int32 [4,2048,2048] -> bitmask. bit=1 -> masked.
// ---------------------------------------------------------------------------
__global__ void __launch_bounds__(256) maskpack_kernel(const int* __restrict__ pad)
{
    size_t w = (size_t)blockIdx.x * 256 + threadIdx.x;
    const int4* p = reinterpret_cast<const int4*>(pad + w * 32);
    uint32_t bits = 0;
    #pragma unroll
    for (int t = 0; t < 8; t++) {
        int4 v = p[t];
        bits |= (uint32_t)(v.x != 0) << (4 * t);
        bits |= (uint32_t)(v.y != 0) << (4 * t + 1);
        bits |= (uint32_t)(v.z != 0) << (4 * t + 2);
        bits |= (uint32_t)(v.w != 0) << (4 * t + 3);
    }
    g_maskbits[w] = bits;
}

// ---------------------------------------------------------------------------
// QKV projection (merged): Y = X @ W + bias, [B,H,S,DK] layout.
// cp.async double-buffered, tf32 MMA, conversion HOISTED to a per-stage pass.
// Block 128x64, warps 2x2 of 32x32.
// ---------------------------------------------------------------------------
__global__ void __launch_bounds__(256) qkv_kernel(
    const float* __restrict__ Q, const float* __restrict__ K, const float* __restrict__ V,
    const float* __restrict__ Wq, const float* __restrict__ Wk, const float* __restrict__ Wv,
    const float* __restrict__ bq, const float* __restrict__ bk, const float* __restrict__ bv)
{
    const int z = blockIdx.z;
    const float* X = (z == 0) ? Q : (z == 1) ? K : V;
    const float* W = (z == 0) ? Wq : (z == 1) ? Wk : Wv;
    const float* bias = (z == 0) ? bq : (z == 1) ? bk : bv;
    float* Y = (z == 0) ? g_q : (z == 1) ? g_k : g_v;

    extern __shared__ float smf[];
    const uint32_t smb = (uint32_t)__cvta_generic_to_shared(smf);

    const int tid = threadIdx.x, wid = tid >> 5, lane = tid & 31;
    const int gid = lane >> 2, tig = lane & 3;
    const int m0 = blockIdx.y * 128, n0 = blockIdx.x * 64;
    const int wm = (wid >> 1) * 32, wn = (wid & 1) * 32;

    float acc[2][4][4] = {};

    #define XS(s,r,c) smf[(s)*8704 + (r)*68 + (c)]
    #define WS(s,r,c) smf[17408 + (s)*4352 + (r)*68 + (c)]
    auto load_chunk = [&](int s, int k0) {
        #pragma unroll
        for (int t = 0; t < 8; t++) {
            int e = (tid + t * 256) * 4, r = e >> 6, c = e & 63;
            cp16(smb + (uint32_t)((s * 8704 + r * 68 + c) * 4),
                 X + (size_t)(m0 + r) * DD + k0 + c);
        }
        #pragma unroll
        for (int t = 0; t < 4; t++) {
            int e = (tid + t * 256) * 4, r = e >> 6, c = e & 63;
            cp16(smb + (uint32_t)((17408 + s * 4352 + r * 68 + c) * 4),
                 W + (size_t)(k0 + r) * DD + n0 + c);
        }
        cp_commit();
    };

    load_chunk(0, 0);
    for (int it = 0; it < 12; it++) {
        if (it + 1 < 12) { load_chunk((it + 1) & 1, (it + 1) * 64); cp_wait<1>(); }
        else cp_wait<0>();
        const int s = it & 1;
        // convert own-copied bytes in place (no sync needed before: same addrs)
        #pragma unroll
        for (int t = 0; t < 8; t++) {
            int e = (tid + t * 256) * 4, r = e >> 6, c = e & 63;
            float4 v = *reinterpret_cast<const float4*>(&XS(s, r, c));
            uint32_t* u = reinterpret_cast<uint32_t*>(&XS(s, r, c));
            u[0] = cvt_tf32(v.x); u[1] = cvt_tf32(v.y);
            u[2] = cvt_tf32(v.z); u[3] = cvt_tf32(v.w);
        }
        #pragma unroll
        for (int t = 0; t < 4; t++) {
            int e = (tid + t * 256) * 4, r = e >> 6, c = e & 63;
            float4 v = *reinterpret_cast<const float4*>(&WS(s, r, c));
            uint32_t* u = reinterpret_cast<uint32_t*>(&WS(s, r, c));
            u[0] = cvt_tf32(v.x); u[1] = cvt_tf32(v.y);
            u[2] = cvt_tf32(v.z); u[3] = cvt_tf32(v.w);
        }
        __syncthreads();
        #pragma unroll
        for (int kk = 0; kk < 64; kk += 8) {
            uint32_t a[2][4], b[4][2];
            #pragma unroll
            for (int mi = 0; mi < 2; mi++) {
                int r = wm + mi * 16 + gid;
                a[mi][0] = __float_as_uint(XS(s, r, kk + tig));
                a[mi][1] = __float_as_uint(XS(s, r + 8, kk + tig));
                a[mi][2] = __float_as_uint(XS(s, r, kk + tig + 4));
                a[mi][3] = __float_as_uint(XS(s, r + 8, kk + tig + 4));
            }
            #pragma unroll
            for (int nj = 0; nj < 4; nj++) {
                int n = wn + nj * 8 + gid;
                b[nj][0] = __float_as_uint(WS(s, kk + tig, n));
                b[nj][1] = __float_as_uint(WS(s, kk + tig + 4, n));
            }
            #pragma unroll
            for (int mi = 0; mi < 2; mi++)
                #pragma unroll
                for (int nj = 0; nj < 4; nj++) mma8(acc[mi][nj], a[mi], b[nj]);
        }
        __syncthreads();
    }
    #undef XS
    #undef WS

    #pragma unroll
    for (int mi = 0; mi < 2; mi++)
        #pragma unroll
        for (int rr = 0; rr < 2; rr++) {
            int r = m0 + wm + mi * 16 + gid + rr * 8;
            #pragma unroll
            for (int nj = 0; nj < 4; nj++) {
                int c = n0 + wn + nj * 8 + tig * 2;
                float v0 = acc[mi][nj][rr * 2 + 0] + bias[c];
                float v1 = acc[mi][nj][rr * 2 + 1] + bias[c + 1];
                int b_ = r / SS, sidx = r % SS, h = c / DKK, d = c % DKK;
                *reinterpret_cast<float2*>(&Y[(((size_t)b_ * HH + h) * SS + sidx) * DKK + d]) =
                    make_float2(v0, v1);
            }
        }
}

// ---------------------------------------------------------------------------
// Scores+exp: 128x128 tile of exp((q.k)/8) (0 if masked) + per-tile row sums.
// Exp tile staged through smem -> coalesced float4 global writes.
// smem: Qs u32[128][68] @0, Ks u32[128][68] @128*68; union Ss f32[128][132] @0.
// ---------------------------------------------------------------------------
__global__ void __launch_bounds__(256) scores_kernel(float* __restrict__ attn_ext)
{
    float* attn = attn_ext ? attn_ext : g_attn_fb;
    extern __shared__ uint32_t smu[];
    uint32_t (*Qs)[68] = reinterpret_cast<uint32_t(*)[68]>(smu);
    uint32_t (*Ks)[68] = reinterpret_cast<uint32_t(*)[68]>(smu + 128 * 68);
    float (*Ss)[132]   = reinterpret_cast<float(*)[132]>(smu);

    const int bh = blockIdx.z, b_ = bh / HH;
    const int q0 = blockIdx.y * 128, k0 = blockIdx.x * 128;
    const int tid = threadIdx.x, wid = tid >> 5, lane = tid & 31;
    const int gid = lane >> 2, tig = lane & 3;
    const int wm = (wid >> 1) * 32, wn = (wid & 1) * 64;

    const float* qp = g_q + ((size_t)bh * SS + q0) * DKK;
    const float* kp = g_k + ((size_t)bh * SS + k0) * DKK;

    #pragma unroll
    for (int t = 0; t < 8; t++) {
        int e = (tid + t * 256) * 4, r = e >> 6, c = e & 63;
        float4 v = *reinterpret_cast<const float4*>(qp + (size_t)r * DKK + c);
        Qs[r][c] = cvt_tf32(v.x); Qs[r][c+1] = cvt_tf32(v.y);
        Qs[r][c+2] = cvt_tf32(v.z); Qs[r][c+3] = cvt_tf32(v.w);
        float4 w = *reinterpret_cast<const float4*>(kp + (size_t)r * DKK + c);
        Ks[r][c] = cvt_tf32(w.x); Ks[r][c+1] = cvt_tf32(w.y);
        Ks[r][c+2] = cvt_tf32(w.z); Ks[r][c+3] = cvt_tf32(w.w);
    }
    __syncthreads();

    float acc[2][8][4] = {};
    #pragma unroll
    for (int kk = 0; kk < 64; kk += 8) {
        uint32_t a[2][4], b[8][2];
        #pragma unroll
        for (int mi = 0; mi < 2; mi++) {
            int r = wm + mi * 16 + gid;
            a[mi][0] = Qs[r][kk + tig];     a[mi][1] = Qs[r + 8][kk + tig];
            a[mi][2] = Qs[r][kk + tig + 4]; a[mi][3] = Qs[r + 8][kk + tig + 4];
        }
        #pragma unroll
        for (int nj = 0; nj < 8; nj++) {
            int n = wn + nj * 8 + gid;
            b[nj][0] = Ks[n][kk + tig]; b[nj][1] = Ks[n][kk + tig + 4];
        }
        #pragma unroll
        for (int mi = 0; mi < 2; mi++)
            #pragma unroll
            for (int nj = 0; nj < 8; nj++) mma8(acc[mi][nj], a[mi], b[nj]);
    }
    __syncthreads();   // all warps done reading Qs/Ks before Ss overwrite

    // exp + mask + psum -> Ss
    #pragma unroll
    for (int mi = 0; mi < 2; mi++)
        #pragma unroll
        for (int rr = 0; rr < 2; rr++) {
            int qrl = wm + mi * 16 + gid + rr * 8;
            int qr = q0 + qrl;
            uint2 mw = *reinterpret_cast<const uint2*>(
                g_maskbits + ((size_t)b_ * SS + qr) * (SS / 32) + (k0 + wn) / 32);
            ull m64 = (ull)mw.x | ((ull)mw.y << 32);
            float rs = 0.f;
            #pragma unroll
            for (int nj = 0; nj < 8; nj++) {
                int j = nj * 8 + tig * 2;
                float v0 = acc[mi][nj][rr * 2 + 0] * 0.125f;
                float v1 = acc[mi][nj][rr * 2 + 1] * 0.125f;
                float p0 = ((m64 >> j) & 1ull) ? 0.f : __expf(v0);
                float p1 = ((m64 >> (j + 1)) & 1ull) ? 0.f : __expf(v1);
                rs += p0 + p1;
                *reinterpret_cast<float2*>(&Ss[qrl][wn + j]) = make_float2(p0, p1);
            }
            rs += __shfl_xor_sync(~0u, rs, 1);
            rs += __shfl_xor_sync(~0u, rs, 2);
            if (tig == 0)
                g_psum[((size_t)bh * SS + qr) * 32 + blockIdx.x * 2 + (wid & 1)] = rs;
        }
    __syncthreads();

    // coalesced writeback
    const size_t base = (size_t)bh * SS * SS;
    #pragma unroll
    for (int t = 0; t < 16; t++) {
        int idx = tid + t * 256;
        int r = idx >> 5, c4 = (idx & 31) * 4;
        float4 v = *reinterpret_cast<const float4*>(&Ss[r][c4]);
        *reinterpret_cast<float4*>(attn + base + (size_t)(q0 + r) * SS + k0 + c4) = v;
    }
}

// ---------------------------------------------------------------------------
// Row-sum reduce -> 1/sum.
// ---------------------------------------------------------------------------
__global__ void __launch_bounds__(256) rowinv_kernel()
{
    size_t idx = (size_t)blockIdx.x * 256 + threadIdx.x;
    const float4* p = reinterpret_cast<const float4*>(g_psum + idx * 32);
    float s = 0.f;
    #pragma unroll
    for (int t = 0; t < 8; t++) { float4 v = p[t]; s += v.x + v.y + v.z + v.w; }
    g_rowinv[idx] = 1.0f / s;
}

// ---------------------------------------------------------------------------
// Context: normalize exp on load (write final attn), MMA with V.
// cp.async double-buffered over 32 k-chunks.
// smem floats: As s*8704 [128][68]; Vs 17408+s*4352 [64][68]; invs @26112[128].
// ---------------------------------------------------------------------------
__global__ void __launch_bounds__(256) context_kernel(float* __restrict__ attn_ext)
{
    float* attn = attn_ext ? attn_ext : g_attn_fb;
    extern __shared__ float smf[];
    const uint32_t smb = (uint32_t)__cvta_generic_to_shared(smf);
    float* invs = smf + 26112;

    const int bh = blockIdx.y, q0 = blockIdx.x * 128;
    const int tid = threadIdx.x, wid = tid >> 5, lane = tid & 31;
    const int gid = lane >> 2, tig = lane & 3;
    const int wm = (wid >> 1) * 32, wn = (wid & 1) * 32;

    float* ap = attn + ((size_t)bh * SS + q0) * SS;
    const float* vp = g_v + (size_t)bh * SS * DKK;

    if (tid < 128) invs[tid] = g_rowinv[(size_t)bh * SS + q0 + tid];

    #define AS(s,r,c) smf[(s)*8704 + (r)*68 + (c)]
    #define VS(s,r,c) smf[17408 + (s)*4352 + (r)*68 + (c)]
    auto load_chunk = [&](int s, int k0) {
        #pragma unroll
        for (int t = 0; t < 8; t++) {
            int e = (tid + t * 256) * 4, r = e >> 6, c = e & 63;
            cp16(smb + (uint32_t)((s * 8704 + r * 68 + c) * 4),
                 ap + (size_t)r * SS + k0 + c);
        }
        #pragma unroll
        for (int t = 0; t < 4; t++) {
            int e = (tid + t * 256) * 4, r = e >> 6, c = e & 63;
            cp16(smb + (uint32_t)((17408 + s * 4352 + r * 68 + c) * 4),
                 vp + (size_t)(k0 + r) * DKK + c);
        }
        cp_commit();
    };

    float acc[2][4][4] = {};
    load_chunk(0, 0);
    for (int it = 0; it < 32; it++) {
        if (it + 1 < 32) { load_chunk((it + 1) & 1, (it + 1) * 64); cp_wait<1>(); }
        else cp_wait<0>();
        __syncthreads();
        const int s = it & 1;
        const int k0 = it * 64;

        // normalize + global writeback + tf32-cvt in place
        #pragma unroll
        for (int t = 0; t < 8; t++) {
            int e = (tid + t * 256) * 4, r = e >> 6, c = e & 63;
            float4 v = *reinterpret_cast<const float4*>(&AS(s, r, c));
            float inv = invs[r];
            v.x *= inv; v.y *= inv; v.z *= inv; v.w *= inv;
            *reinterpret_cast<float4*>(ap + (size_t)r * SS + k0 + c) = v;
            uint32_t* u = reinterpret_cast<uint32_t*>(&AS(s, r, c));
            u[0] = cvt_tf32(v.x); u[1] = cvt_tf32(v.y);
            u[2] = cvt_tf32(v.z); u[3] = cvt_tf32(v.w);
        }
        #pragma unroll
        for (int t = 0; t < 4; t++) {
            int e = (tid + t * 256) * 4, r = e >> 6, c = e & 63;
            float4 v = *reinterpret_cast<const float4*>(&VS(s, r, c));
            uint32_t* u = reinterpret_cast<uint32_t*>(&VS(s, r, c));
            u[0] = cvt_tf32(v.x); u[1] = cvt_tf32(v.y);
            u[2] = cvt_tf32(v.z); u[3] = cvt_tf32(v.w);
        }
        __syncthreads();

        #pragma unroll
        for (int kk = 0; kk < 64; kk += 8) {
            uint32_t a[2][4], b[4][2];
            #pragma unroll
            for (int mi = 0; mi < 2; mi++) {
                int r = wm + mi * 16 + gid;
                a[mi][0] = __float_as_uint(AS(s, r, kk + tig));
                a[mi][1] = __float_as_uint(AS(s, r + 8, kk + tig));
                a[mi][2] = __float_as_uint(AS(s, r, kk + tig + 4));
                a[mi][3] = __float_as_uint(AS(s, r + 8, kk + tig + 4));
            }
            #pragma unroll
            for (int nj = 0; nj < 4; nj++) {
                int n = wn + nj * 8 + gid;
                b[nj][0] = __float_as_uint(VS(s, kk + tig, n));
                b[nj][1] = __float_as_uint(VS(s, kk + tig + 4, n));
            }
            #pragma unroll
            for (int mi = 0; mi < 2; mi++)
                #pragma unroll
                for (int nj = 0; nj < 4; nj++) mma8(acc[mi][nj], a[mi], b[nj]);
        }
        __syncthreads();
    }
    #undef AS
    #undef VS

    const int b_ = bh / HH, h = bh % HH;
    #pragma unroll
    for (int mi = 0; mi < 2; mi++)
        #pragma unroll
        for (int rr = 0; rr < 2; rr++) {
            int s = q0 + wm + mi * 16 + gid + rr * 8;
            #pragma unroll
            for (int nj = 0; nj < 4; nj++) {
                int d = wn + nj * 8 + tig * 2;
                *reinterpret_cast<float2*>(&g_ctx[((size_t)b_ * SS + s) * DD + h * DKK + d]) =
                    make_float2(acc[mi][nj][rr * 2], acc[mi][nj][rr * 2 + 1]);
            }
        }
}

// ---------------------------------------------------------------------------
// Output projection: g_pre = g_ctx @ Wo + bo + resid. Conversion hoisted.
// ---------------------------------------------------------------------------
__global__ void __launch_bounds__(256) outproj_kernel(
    const float* __restrict__ W, const float* __restrict__ bias,
    const float* __restrict__ resid)
{
    const float* X = g_ctx;
    extern __shared__ float smf[];
    const uint32_t smb = (uint32_t)__cvta_generic_to_shared(smf);

    const int tid = threadIdx.x, wid = tid >> 5, lane = tid & 31;
    const int gid = lane >> 2, tig = lane & 3;
    const int m0 = blockIdx.y * 128, n0 = blockIdx.x * 64;
    const int wm = (wid >> 1) * 32, wn = (wid & 1) * 32;

    float acc[2][4][4] = {};

    #define XS(s,r,c) smf[(s)*8704 + (r)*68 + (c)]
    #define WS(s,r,c) smf[17408 + (s)*4352 + (r)*68 + (c)]
    auto load_chunk = [&](int s, int k0) {
        #pragma unroll
        for (int t = 0; t < 8; t++) {
            int e = (tid + t * 256) * 4, r = e >> 6, c = e & 63;
            cp16(smb + (uint32_t)((s * 8704 + r * 68 + c) * 4),
                 X + (size_t)(m0 + r) * DD + k0 + c);
        }
        #pragma unroll
        for (int t = 0; t < 4; t++) {
            int e = (tid + t * 256) * 4, r = e >> 6, c = e & 63;
            cp16(smb + (uint32_t)((17408 + s * 4352 + r * 68 + c) * 4),
                 W + (size_t)(k0 + r) * DD + n0 + c);
        }
        cp_commit();
    };

    load_chunk(0, 0);
    for (int it = 0; it < 12; it++) {
        if (it + 1 < 12) { load_chunk((it + 1) & 1, (it + 1) * 64); cp_wait<1>(); }
        else cp_wait<0>();
        const int s = it & 1;
        #pragma unroll
        for (int t = 0; t < 8; t++) {
            int e = (tid + t * 256) * 4, r = e >> 6, c = e & 63;
            float4 v = *reinterpret_cast<const float4*>(&XS(s, r, c));
            uint32_t* u = reinterpret_cast<uint32_t*>(&XS(s, r, c));
            u[0] = cvt_tf32(v.x); u[1] = cvt_tf32(v.y);
            u[2] = cvt_tf32(v.z); u[3] = cvt_tf32(v.w);
        }
        #pragma unroll
        for (int t = 0; t < 4; t++) {
            int e = (tid + t * 256) * 4, r = e >> 6, c = e & 63;
            float4 v = *reinterpret_cast<const float4*>(&WS(s, r, c));
            uint32_t* u = reinterpret_cast<uint32_t*>(&WS(s, r, c));
            u[0] = cvt_tf32(v.x); u[1] = cvt_tf32(v.y);
            u[2] = cvt_tf32(v.z); u[3] = cvt_tf32(v.w);
        }
        __syncthreads();
        #pragma unroll
        for (int kk = 0; kk < 64; kk += 8) {
            uint32_t a[2][4], b[4][2];
            #pragma unroll
            for (int mi = 0; mi < 2; mi++) {
                int r = wm + mi * 16 + gid;
                a[mi][0] = __float_as_uint(XS(s, r, kk + tig));
                a[mi][1] = __float_as_uint(XS(s, r + 8, kk + tig));
                a[mi][2] = __float_as_uint(XS(s, r, kk + tig + 4));
                a[mi][3] = __float_as_uint(XS(s, r + 8, kk + tig + 4));
            }
            #pragma unroll
            for (int nj = 0; nj < 4; nj++) {
                int n = wn + nj * 8 + gid;
                b[nj][0] = __float_as_uint(WS(s, kk + tig, n));
                b[nj][1] = __float_as_uint(WS(s, kk + tig + 4, n));
            }
            #pragma unroll
            for (int mi = 0; mi < 2; mi++)
                #pragma unroll
                for (int nj = 0; nj < 4; nj++) mma8(acc[mi][nj], a[mi], b[nj]);
        }
        __syncthreads();
    }
    #undef XS
    #undef WS

    #pragma unroll
    for (int mi = 0; mi < 2; mi++)
        #pragma unroll
        for (int rr = 0; rr < 2; rr++) {
            int r = m0 + wm + mi * 16 + gid + rr * 8;
            #pragma unroll
            for (int nj = 0; nj < 4; nj++) {
                int c = n0 + wn + nj * 8 + tig * 2;
                float v0 = acc[mi][nj][rr * 2 + 0] + bias[c];
                float v1 = acc[mi][nj][rr * 2 + 1] + bias[c + 1];
                const float2 rs = *reinterpret_cast<const float2*>(&resid[(size_t)r * DD + c]);
                *reinterpret_cast<float2*>(&g_pre[(size_t)r * DD + c]) =
                    make_float2(v0 + rs.x, v1 + rs.y);
            }
        }
}

// ---------------------------------------------------------------------------
// LayerNorm over D=768.
// ---------------------------------------------------------------------------
__global__ void __launch_bounds__(256) ln_kernel(
    const float* __restrict__ lg, const float* __restrict__ lb, float* __restrict__ out)
{
    const size_t row = blockIdx.x;
    const float* x = g_pre + row * DD;
    const int tid = threadIdx.x;
    __shared__ float red[8];

    float v[3];
    float s = 0.f;
    #pragma unroll
    for (int t = 0; t < 3; t++) { v[t] = x[tid + t * 256]; s += v[t]; }
    #pragma unroll
    for (int o = 16; o; o >>= 1) s += __shfl_xor_sync(~0u, s, o);
    if ((tid & 31) == 0) red[tid >> 5] = s;
    __syncthreads();
    s = 0.f;
    #pragma unroll
    for (int w = 0; w < 8; w++) s += red[w];
    const float mu = s * (1.0f / DD);
    __syncthreads();

    float var = 0.f;
    #pragma unroll
    for (int t = 0; t < 3; t++) { float d = v[t] - mu; var += d * d; }
    #pragma unroll
    for (int o = 16; o; o >>= 1) var += __shfl_xor_sync(~0u, var, o);
    if ((tid & 31) == 0) red[tid >> 5] = var;
    __syncthreads();
    var = 0.f;
    #pragma unroll
    for (int w = 0; w < 8; w++) var += red[w];
    const float inv = rsqrtf(var * (1.0f / DD) + 1e-5f);

    #pragma unroll
    for (int t = 0; t < 3; t++) {
        int c = tid + t * 256;
        out[row * DD + c] = (v[t] - mu) * inv * lg[c] + lb[c];
    }
}

// ---------------------------------------------------------------------------
extern "C" void kernel_launch(void* const* d_in, const int* in_sizes, int n_in,
                              void* d_out, int out_size)
{
    const float* Q  = (const float*)d_in[0];
    const float* K  = (const float*)d_in[1];
    const float* V  = (const float*)d_in[2];
    const int*   pad = (const int*)d_in[3];
    const float* Wq = (const float*)d_in[4];
    const float* bq = (const float*)d_in[5];
    const float* Wk = (const float*)d_in[6];
    const float* bk = (const float*)d_in[7];
    const float* Wv = (const float*)d_in[8];
    const float* bv = (const float*)d_in[9];
    const float* Wo = (const float*)d_in[10];
    const float* bo = (const float*)d_in[11];
    const float* lg = (const float*)d_in[12];
    const float* lb = (const float*)d_in[13];
    float* out = (float*)d_out;

    float* attn = ((long long)out_size >= OUT_ELEMS + ATTN_ELEMS) ? (out + OUT_ELEMS)
                                                                  : nullptr;

    const int GEMM_SMEM   = 26112 * 4;   // 104448
    const int SCORES_SMEM = 17408 * 4;   // 69632
    const int CTX_SMEM    = 26240 * 4;   // 104960
    cudaFuncSetAttribute(qkv_kernel, cudaFuncAttributeMaxDynamicSharedMemorySize, GEMM_SMEM);
    cudaFuncSetAttribute(outproj_kernel, cudaFuncAttributeMaxDynamicSharedMemorySize, GEMM_SMEM);
    cudaFuncSetAttribute(scores_kernel, cudaFuncAttributeMaxDynamicSharedMemorySize, SCORES_SMEM);
    cudaFuncSetAttribute(context_kernel, cudaFuncAttributeMaxDynamicSharedMemorySize, CTX_SMEM);

    maskpack_kernel<<<(BB * SS * (SS / 32)) / 256, 256>>>(pad);

    dim3 gq(DD / 64, (BB * SS) / 128, 3);       // (12, 64, 3)
    qkv_kernel<<<gq, 256, GEMM_SMEM>>>(Q, K, V, Wq, Wk, Wv, bq, bk, bv);

    dim3 gs(SS / 128, SS / 128, BB * HH);       // (16, 16, 48)
    scores_kernel<<<gs, 256, SCORES_SMEM>>>(attn);

    rowinv_kernel<<<(BB * HH * SS) / 256, 256>>>();

    dim3 gc(SS / 128, BB * HH);                 // (16, 48)
    context_kernel<<<gc, 256, CTX_SMEM>>>(attn);

    dim3 gp(DD / 64, (BB * SS) / 128);          // (12, 64)
    outproj_kernel<<<gp, 256, GEMM_SMEM>>>(Wo, bo, Q);

    ln_kernel<<<BB * SS, 256>>>(lg, lb, out);
}

// round 11
// speedup vs baseline: 1.1590x; 1.0239x over previous
#include <cuda_runtime.h>
#include <cstdint>
#include <math.h>

#define BB 4
#define SS 2048
#define DD 768
#define HH 12
#define DKK 64

typedef unsigned long long ull;

static const long long OUT_ELEMS  = (long long)BB * SS * DD;
static const long long ATTN_ELEMS = (long long)BB * HH * SS * SS;

// octet permutation: logical k -> physical slot (within groups of 8)
#define PHYS8(k) (((k) & ~7) | (((k) & 3) << 1) | (((k) >> 2) & 1))

// Scratch
__device__ float g_q[BB * HH * SS * DKK];     // rounded + k-permuted
__device__ float g_k[BB * HH * SS * DKK];     // rounded + k-permuted
__device__ float g_v[BB * HH * SS * DKK];     // rounded, plain layout
__device__ float g_ctx[BB * SS * DD];         // rounded + k-permuted
__device__ float g_pre[BB * SS * DD];
__device__ float g_psum[(size_t)BB * HH * SS * 32];
__device__ float g_rowinv[(size_t)BB * HH * SS];
__device__ uint32_t g_maskbits[(size_t)BB * SS * (SS / 32)];
__device__ float g_attn_fb[(long long)BB * HH * SS * SS];
__device__ float g_wTp[4][DD * DD];           // [n][k] transposed, rounded, permuted
__device__ float g_xr[3][BB * SS * DD];       // rounded + permuted Q/K/V inputs

__device__ __forceinline__ uint32_t cvt_tf32(float x) {
    uint32_t u; asm("cvt.rna.tf32.f32 %0, %1;" : "=r"(u) : "f"(x)); return u;
}
__device__ __forceinline__ float rnd(float x) { return __uint_as_float(cvt_tf32(x)); }

__device__ __forceinline__ void mma8(float* c, const uint32_t* a, const uint32_t* b) {
    asm("mma.sync.aligned.m16n8k8.row.col.f32.tf32.tf32.f32 "
        "{%0,%1,%2,%3},{%4,%5,%6,%7},{%8,%9},{%0,%1,%2,%3};"
        : "+f"(c[0]), "+f"(c[1]), "+f"(c[2]), "+f"(c[3])
        : "r"(a[0]), "r"(a[1]), "r"(a[2]), "r"(a[3]), "r"(b[0]), "r"(b[1]));
}

__device__ __forceinline__ void cp16(uint32_t dst, const void* src) {
    asm volatile("cp.async.cg.shared.global [%0], [%1], 16;" :: "r"(dst), "l"(src));
}
__device__ __forceinline__ void cp_commit() { asm volatile("cp.async.commit_group;"); }
template<int N> __device__ __forceinline__ void cp_wait() {
    asm volatile("cp.async.wait_group %0;" :: "n"(N));
}

// ---------------------------------------------------------------------------
// Mask bit-pack: int32 [4,2048,2048] -> bitmask. bit=1 -> masked.
// ---------------------------------------------------------------------------
__global__ void __launch_bounds__(256) maskpack_kernel(const int* __restrict__ pad)
{
    size_t w = (size_t)blockIdx.x * 256 + threadIdx.x;
    const int4* p = reinterpret_cast<const int4*>(pad + w * 32);
    uint32_t bits = 0;
    #pragma unroll
    for (int t = 0; t < 8; t++) {
        int4 v = p[t];
        bits |= (uint32_t)(v.x != 0) << (4 * t);
        bits |= (uint32_t)(v.y != 0) << (4 * t + 1);
        bits |= (uint32_t)(v.z != 0) << (4 * t + 2);
        bits |= (uint32_t)(v.w != 0) << (4 * t + 3);
    }
    g_maskbits[w] = bits;
}

// ---------------------------------------------------------------------------
// Weight transpose + round + k-permute: g_wTp[z][n*DD + PHYS8(k)] = rna(W[k][n]).
// ---------------------------------------------------------------------------
__global__ void __launch_bounds__(256) wtrans_kernel(
    const float* __restrict__ Wq, const float* __restrict__ Wk,
    const float* __restrict__ Wv, const float* __restrict__ Wo)
{
    const float* W = (blockIdx.z == 0) ? Wq : (blockIdx.z == 1) ? Wk
                   : (blockIdx.z == 2) ? Wv : Wo;
    float* T = g_wTp[blockIdx.z];
    __shared__ float tile[32][33];
    int k0 = blockIdx.y * 32, n0 = blockIdx.x * 32;
    int tx = threadIdx.x & 31, ty = threadIdx.x >> 5;
    #pragma unroll
    for (int i = 0; i < 4; i++)
        tile[ty + i * 8][tx] = W[(size_t)(k0 + ty + i * 8) * DD + n0 + tx];
    __syncthreads();
    #pragma unroll
    for (int i = 0; i < 4; i++)
        T[(size_t)(n0 + ty + i * 8) * DD + k0 + PHYS8(tx)] = rnd(tile[tx][ty + i * 8]);
}

// ---------------------------------------------------------------------------
// Round + permute X inputs: one thread per octet; stores stay float4.
// phys octet = [l0,l4,l1,l5,l2,l6,l3,l7].
// ---------------------------------------------------------------------------
__global__ void __launch_bounds__(256) roundperm_kernel(
    const float* __restrict__ Q, const float* __restrict__ K, const float* __restrict__ V)
{
    const float* X = (blockIdx.y == 0) ? Q : (blockIdx.y == 1) ? K : V;
    float* O = g_xr[blockIdx.y];
    size_t o = (size_t)blockIdx.x * 256 + threadIdx.x;   // octet index
    const float4* p = reinterpret_cast<const float4*>(X) + o * 2;
    float4 lo = p[0], hi = p[1];
    float4 o0 = make_float4(rnd(lo.x), rnd(hi.x), rnd(lo.y), rnd(hi.y));
    float4 o1 = make_float4(rnd(lo.z), rnd(hi.z), rnd(lo.w), rnd(hi.w));
    float4* q = reinterpret_cast<float4*>(O) + o * 2;
    q[0] = o0; q[1] = o1;
}

// ---------------------------------------------------------------------------
// QKV projection (merged): Y = X @ W + bias, [B,H,S,DK] layout.
// X/W pre-rounded + k-permuted -> all fragment loads are LDS.64, no cvts.
// q/k written rounded+permuted; v written rounded plain.
// ---------------------------------------------------------------------------
__global__ void __launch_bounds__(256) qkv_kernel(
    const float* __restrict__ bq, const float* __restrict__ bk, const float* __restrict__ bv)
{
    const int z = blockIdx.z;
    const float* X = g_xr[z];
    const float* W = g_wTp[z];
    const float* bias = (z == 0) ? bq : (z == 1) ? bk : bv;
    float* Y = (z == 0) ? g_q : (z == 1) ? g_k : g_v;

    extern __shared__ float smf[];
    const uint32_t smb = (uint32_t)__cvta_generic_to_shared(smf);

    const int tid = threadIdx.x, wid = tid >> 5, lane = tid & 31;
    const int gid = lane >> 2, tig = lane & 3;
    const int m0 = blockIdx.y * 128, n0 = blockIdx.x * 64;
    const int wm = (wid >> 1) * 32, wn = (wid & 1) * 32;

    float acc[2][4][4] = {};

    #define XS(s,r,c) smf[(s)*8704 + (r)*68 + (c)]
    #define WS(s,r,c) smf[17408 + (s)*4352 + (r)*68 + (c)]   // [n][k]
    auto load_chunk = [&](int s, int k0) {
        #pragma unroll
        for (int t = 0; t < 8; t++) {
            int idx = tid + t * 256, r = idx >> 4, g = idx & 15;
            cp16(smb + (uint32_t)((s * 8704 + r * 68 + g * 4) * 4),
                 X + (size_t)(m0 + r) * DD + k0 + g * 4);
        }
        #pragma unroll
        for (int t = 0; t < 4; t++) {
            int idx = tid + t * 256, r = idx >> 4, g = idx & 15;
            cp16(smb + (uint32_t)((17408 + s * 4352 + r * 68 + g * 4) * 4),
                 W + (size_t)(n0 + r) * DD + k0 + g * 4);
        }
        cp_commit();
    };

    load_chunk(0, 0);
    for (int it = 0; it < 12; it++) {
        if (it + 1 < 12) { load_chunk((it + 1) & 1, (it + 1) * 64); cp_wait<1>(); }
        else cp_wait<0>();
        __syncthreads();
        const int s = it & 1;
        #pragma unroll
        for (int kk = 0; kk < 64; kk += 8) {
            uint32_t a[2][4], b[4][2];
            #pragma unroll
            for (int mi = 0; mi < 2; mi++) {
                int r = wm + mi * 16 + gid;
                uint2 la = *reinterpret_cast<const uint2*>(&XS(s, r, kk + 2 * tig));
                uint2 lb = *reinterpret_cast<const uint2*>(&XS(s, r + 8, kk + 2 * tig));
                a[mi][0] = la.x; a[mi][1] = lb.x; a[mi][2] = la.y; a[mi][3] = lb.y;
            }
            #pragma unroll
            for (int nj = 0; nj < 4; nj++) {
                int n = wn + nj * 8 + gid;
                uint2 w2 = *reinterpret_cast<const uint2*>(&WS(s, n, kk + 2 * tig));
                b[nj][0] = w2.x; b[nj][1] = w2.y;
            }
            #pragma unroll
            for (int mi = 0; mi < 2; mi++)
                #pragma unroll
                for (int nj = 0; nj < 4; nj++) mma8(acc[mi][nj], a[mi], b[nj]);
        }
        __syncthreads();
    }
    #undef XS
    #undef WS

    #pragma unroll
    for (int mi = 0; mi < 2; mi++)
        #pragma unroll
        for (int rr = 0; rr < 2; rr++) {
            int r = m0 + wm + mi * 16 + gid + rr * 8;
            int b_ = r >> 11, sidx = r & 2047;
            #pragma unroll
            for (int nj = 0; nj < 4; nj++) {
                int c = n0 + wn + nj * 8 + tig * 2;
                float v0 = rnd(acc[mi][nj][rr * 2 + 0] + bias[c]);
                float v1 = rnd(acc[mi][nj][rr * 2 + 1] + bias[c + 1]);
                int h = c >> 6, d = c & 63;
                float* o = Y + (((size_t)b_ * HH + h) * SS + sidx) * DKK;
                if (z == 2) {
                    *reinterpret_cast<float2*>(o + d) = make_float2(v0, v1);
                } else {
                    o[PHYS8(d)] = v0;
                    o[PHYS8(d + 1)] = v1;
                }
            }
        }
}

// ---------------------------------------------------------------------------
// Scores+exp: q/k pre-rounded + permuted -> raw uint4 staging, LDS.64 frags.
// ---------------------------------------------------------------------------
__global__ void __launch_bounds__(256) scores_kernel(float* __restrict__ attn_ext)
{
    float* attn = attn_ext ? attn_ext : g_attn_fb;
    extern __shared__ uint32_t smu[];
    uint32_t (*Qs)[68] = reinterpret_cast<uint32_t(*)[68]>(smu);
    uint32_t (*Ks)[68] = reinterpret_cast<uint32_t(*)[68]>(smu + 128 * 68);
    float (*Ss)[132]   = reinterpret_cast<float(*)[132]>(smu);

    const int bh = blockIdx.z, b_ = bh / HH;
    const int q0 = blockIdx.y * 128, k0 = blockIdx.x * 128;
    const int tid = threadIdx.x, wid = tid >> 5, lane = tid & 31;
    const int gid = lane >> 2, tig = lane & 3;
    const int wm = (wid >> 1) * 32, wn = (wid & 1) * 64;

    const float* qp = g_q + ((size_t)bh * SS + q0) * DKK;
    const float* kp = g_k + ((size_t)bh * SS + k0) * DKK;

    #pragma unroll
    for (int t = 0; t < 8; t++) {
        int e = (tid + t * 256) * 4, r = e >> 6, c = e & 63;
        *reinterpret_cast<uint4*>(&Qs[r][c]) =
            *reinterpret_cast<const uint4*>(qp + (size_t)r * DKK + c);
        *reinterpret_cast<uint4*>(&Ks[r][c]) =
            *reinterpret_cast<const uint4*>(kp + (size_t)r * DKK + c);
    }
    __syncthreads();

    float acc[2][8][4] = {};
    #pragma unroll
    for (int kk = 0; kk < 64; kk += 8) {
        uint32_t a[2][4], b[8][2];
        #pragma unroll
        for (int mi = 0; mi < 2; mi++) {
            int r = wm + mi * 16 + gid;
            uint2 la = *reinterpret_cast<const uint2*>(&Qs[r][kk + 2 * tig]);
            uint2 lb = *reinterpret_cast<const uint2*>(&Qs[r + 8][kk + 2 * tig]);
            a[mi][0] = la.x; a[mi][1] = lb.x; a[mi][2] = la.y; a[mi][3] = lb.y;
        }
        #pragma unroll
        for (int nj = 0; nj < 8; nj++) {
            int n = wn + nj * 8 + gid;
            uint2 kb = *reinterpret_cast<const uint2*>(&Ks[n][kk + 2 * tig]);
            b[nj][0] = kb.x; b[nj][1] = kb.y;
        }
        #pragma unroll
        for (int mi = 0; mi < 2; mi++)
            #pragma unroll
            for (int nj = 0; nj < 8; nj++) mma8(acc[mi][nj], a[mi], b[nj]);
    }
    __syncthreads();

    #pragma unroll
    for (int mi = 0; mi < 2; mi++)
        #pragma unroll
        for (int rr = 0; rr < 2; rr++) {
            int qrl = wm + mi * 16 + gid + rr * 8;
            int qr = q0 + qrl;
            uint2 mw = *reinterpret_cast<const uint2*>(
                g_maskbits + ((size_t)b_ * SS + qr) * (SS / 32) + (k0 + wn) / 32);
            ull m64 = (ull)mw.x | ((ull)mw.y << 32);
            float rs = 0.f;
            #pragma unroll
            for (int nj = 0; nj < 8; nj++) {
                int j = nj * 8 + tig * 2;
                float v0 = acc[mi][nj][rr * 2 + 0] * 0.125f;
                float v1 = acc[mi][nj][rr * 2 + 1] * 0.125f;
                float p0 = ((m64 >> j) & 1ull) ? 0.f : __expf(v0);
                float p1 = ((m64 >> (j + 1)) & 1ull) ? 0.f : __expf(v1);
                rs += p0 + p1;
                *reinterpret_cast<float2*>(&Ss[qrl][wn + j]) = make_float2(p0, p1);
            }
            rs += __shfl_xor_sync(~0u, rs, 1);
            rs += __shfl_xor_sync(~0u, rs, 2);
            if (tig == 0)
                g_psum[((size_t)bh * SS + qr) * 32 + blockIdx.x * 2 + (wid & 1)] = rs;
        }
    __syncthreads();

    const size_t base = (size_t)bh * SS * SS;
    #pragma unroll
    for (int t = 0; t < 16; t++) {
        int idx = tid + t * 256;
        int r = idx >> 5, c4 = (idx & 31) * 4;
        float4 v = *reinterpret_cast<const float4*>(&Ss[r][c4]);
        *reinterpret_cast<float4*>(attn + base + (size_t)(q0 + r) * SS + k0 + c4) = v;
    }
}

// ---------------------------------------------------------------------------
__global__ void __launch_bounds__(256) rowinv_kernel()
{
    size_t idx = (size_t)blockIdx.x * 256 + threadIdx.x;
    const float4* p = reinterpret_cast<const float4*>(g_psum + idx * 32);
    float s = 0.f;
    #pragma unroll
    for (int t = 0; t < 8; t++) { float4 v = p[t]; s += v.x + v.y + v.z + v.w; }
    g_rowinv[idx] = 1.0f / s;
}

// ---------------------------------------------------------------------------
// Context: normalize exp on load (write final attn), MMA with V.
// V pre-rounded (no cvt pass). g_ctx written rounded + k-permuted.
// ---------------------------------------------------------------------------
__global__ void __launch_bounds__(256) context_kernel(float* __restrict__ attn_ext)
{
    float* attn = attn_ext ? attn_ext : g_attn_fb;
    extern __shared__ float smf[];
    const uint32_t smb = (uint32_t)__cvta_generic_to_shared(smf);
    float* invs = smf + 26112;

    const int bh = blockIdx.y, q0 = blockIdx.x * 128;
    const int tid = threadIdx.x, wid = tid >> 5, lane = tid & 31;
    const int gid = lane >> 2, tig = lane & 3;
    const int wm = (wid >> 1) * 32, wn = (wid & 1) * 32;

    float* ap = attn + ((size_t)bh * SS + q0) * SS;
    const float* vp = g_v + (size_t)bh * SS * DKK;

    if (tid < 128) invs[tid] = g_rowinv[(size_t)bh * SS + q0 + tid];

    #define AS(s,r,c) smf[(s)*8704 + (r)*68 + (c)]
    #define VS(s,r,c) smf[17408 + (s)*4352 + (r)*68 + (c)]
    auto load_chunk = [&](int s, int k0) {
        #pragma unroll
        for (int t = 0; t < 8; t++) {
            int e = (tid + t * 256) * 4, r = e >> 6, c = e & 63;
            cp16(smb + (uint32_t)((s * 8704 + r * 68 + c) * 4),
                 ap + (size_t)r * SS + k0 + c);
        }
        #pragma unroll
        for (int t = 0; t < 4; t++) {
            int e = (tid + t * 256) * 4, r = e >> 6, c = e & 63;
            cp16(smb + (uint32_t)((17408 + s * 4352 + r * 68 + c) * 4),
                 vp + (size_t)(k0 + r) * DKK + c);
        }
        cp_commit();
    };

    float acc[2][4][4] = {};
    load_chunk(0, 0);
    for (int it = 0; it < 32; it++) {
        if (it + 1 < 32) { load_chunk((it + 1) & 1, (it + 1) * 64); cp_wait<1>(); }
        else cp_wait<0>();
        __syncthreads();
        const int s = it & 1;
        const int k0 = it * 64;

        // normalize + global writeback + tf32-cvt in place (attn only)
        #pragma unroll
        for (int t = 0; t < 8; t++) {
            int e = (tid + t * 256) * 4, r = e >> 6, c = e & 63;
            float4 v = *reinterpret_cast<const float4*>(&AS(s, r, c));
            float inv = invs[r];
            v.x *= inv; v.y *= inv; v.z *= inv; v.w *= inv;
            *reinterpret_cast<float4*>(ap + (size_t)r * SS + k0 + c) = v;
            uint32_t* u = reinterpret_cast<uint32_t*>(&AS(s, r, c));
            u[0] = cvt_tf32(v.x); u[1] = cvt_tf32(v.y);
            u[2] = cvt_tf32(v.z); u[3] = cvt_tf32(v.w);
        }
        __syncthreads();

        #pragma unroll
        for (int kk = 0; kk < 64; kk += 8) {
            uint32_t a[2][4], b[4][2];
            #pragma unroll
            for (int mi = 0; mi < 2; mi++) {
                int r = wm + mi * 16 + gid;
                a[mi][0] = __float_as_uint(AS(s, r, kk + tig));
                a[mi][1] = __float_as_uint(AS(s, r + 8, kk + tig));
                a[mi][2] = __float_as_uint(AS(s, r, kk + tig + 4));
                a[mi][3] = __float_as_uint(AS(s, r + 8, kk + tig + 4));
            }
            #pragma unroll
            for (int nj = 0; nj < 4; nj++) {
                int n = wn + nj * 8 + gid;
                b[nj][0] = __float_as_uint(VS(s, kk + tig, n));
                b[nj][1] = __float_as_uint(VS(s, kk + tig + 4, n));
            }
            #pragma unroll
            for (int mi = 0; mi < 2; mi++)
                #pragma unroll
                for (int nj = 0; nj < 4; nj++) mma8(acc[mi][nj], a[mi], b[nj]);
        }
        __syncthreads();
    }
    #undef AS
    #undef VS

    const int b_ = bh / HH, h = bh % HH;
    #pragma unroll
    for (int mi = 0; mi < 2; mi++)
        #pragma unroll
        for (int rr = 0; rr < 2; rr++) {
            int s = q0 + wm + mi * 16 + gid + rr * 8;
            #pragma unroll
            for (int nj = 0; nj < 4; nj++) {
                int d = wn + nj * 8 + tig * 2;
                float r0 = rnd(acc[mi][nj][rr * 2]);
                float r1 = rnd(acc[mi][nj][rr * 2 + 1]);
                float* o = &g_ctx[((size_t)b_ * SS + s) * DD + h * DKK];
                o[PHYS8(d)] = r0;
                o[PHYS8(d + 1)] = r1;
            }
        }
}

// ---------------------------------------------------------------------------
// Output projection: g_pre = g_ctx @ Wo + bo + resid (fp32 output).
// g_ctx / Wo pre-rounded + permuted -> LDS.64 fragments, no cvts.
// ---------------------------------------------------------------------------
__global__ void __launch_bounds__(256) outproj_kernel(
    const float* __restrict__ bias, const float* __restrict__ resid)
{
    const float* X = g_ctx;
    const float* W = g_wTp[3];
    extern __shared__ float smf[];
    const uint32_t smb = (uint32_t)__cvta_generic_to_shared(smf);

    const int tid = threadIdx.x, wid = tid >> 5, lane = tid & 31;
    const int gid = lane >> 2, tig = lane & 3;
    const int m0 = blockIdx.y * 128, n0 = blockIdx.x * 64;
    const int wm = (wid >> 1) * 32, wn = (wid & 1) * 32;

    float acc[2][4][4] = {};

    #define XS(s,r,c) smf[(s)*8704 + (r)*68 + (c)]
    #define WS(s,r,c) smf[17408 + (s)*4352 + (r)*68 + (c)]
    auto load_chunk = [&](int s, int k0) {
        #pragma unroll
        for (int t = 0; t < 8; t++) {
            int idx = tid + t * 256, r = idx >> 4, g = idx & 15;
            cp16(smb + (uint32_t)((s * 8704 + r * 68 + g * 4) * 4),
                 X + (size_t)(m0 + r) * DD + k0 + g * 4);
        }
        #pragma unroll
        for (int t = 0; t < 4; t++) {
            int idx = tid + t * 256, r = idx >> 4, g = idx & 15;
            cp16(smb + (uint32_t)((17408 + s * 4352 + r * 68 + g * 4) * 4),
                 W + (size_t)(n0 + r) * DD + k0 + g * 4);
        }
        cp_commit();
    };

    load_chunk(0, 0);
    for (int it = 0; it < 12; it++) {
        if (it + 1 < 12) { load_chunk((it + 1) & 1, (it + 1) * 64); cp_wait<1>(); }
        else cp_wait<0>();
        __syncthreads();
        const int s = it & 1;
        #pragma unroll
        for (int kk = 0; kk < 64; kk += 8) {
            uint32_t a[2][4], b[4][2];
            #pragma unroll
            for (int mi = 0; mi < 2; mi++) {
                int r = wm + mi * 16 + gid;
                uint2 la = *reinterpret_cast<const uint2*>(&XS(s, r, kk + 2 * tig));
                uint2 lb = *reinterpret_cast<const uint2*>(&XS(s, r + 8, kk + 2 * tig));
                a[mi][0] = la.x; a[mi][1] = lb.x; a[mi][2] = la.y; a[mi][3] = lb.y;
            }
            #pragma unroll
            for (int nj = 0; nj < 4; nj++) {
                int n = wn + nj * 8 + gid;
                uint2 w2 = *reinterpret_cast<const uint2*>(&WS(s, n, kk + 2 * tig));
                b[nj][0] = w2.x; b[nj][1] = w2.y;
            }
            #pragma unroll
            for (int mi = 0; mi < 2; mi++)
                #pragma unroll
                for (int nj = 0; nj < 4; nj++) mma8(acc[mi][nj], a[mi], b[nj]);
        }
        __syncthreads();
    }
    #undef XS
    #undef WS

    #pragma unroll
    for (int mi = 0; mi < 2; mi++)
        #pragma unroll
        for (int rr = 0; rr < 2; rr++) {
            int r = m0 + wm + mi * 16 + gid + rr * 8;
            #pragma unroll
            for (int nj = 0; nj < 4; nj++) {
                int c = n0 + wn + nj * 8 + tig * 2;
                float v0 = acc[mi][nj][rr * 2 + 0] + bias[c];
                float v1 = acc[mi][nj][rr * 2 + 1] + bias[c + 1];
                const float2 rs = *reinterpret_cast<const float2*>(&resid[(size_t)r * DD + c]);
                *reinterpret_cast<float2*>(&g_pre[(size_t)r * DD + c]) =
                    make_float2(v0 + rs.x, v1 + rs.y);
            }
        }
}

// ---------------------------------------------------------------------------
// LayerNorm over D=768.
// ---------------------------------------------------------------------------
__global__ void __launch_bounds__(256) ln_kernel(
    const float* __restrict__ lg, const float* __restrict__ lb, float* __restrict__ out)
{
    const size_t row = blockIdx.x;
    const float* x = g_pre + row * DD;
    const int tid = threadIdx.x;
    __shared__ float red[8];

    float v[3];
    float s = 0.f;
    #pragma unroll
    for (int t = 0; t < 3; t++) { v[t] = x[tid + t * 256]; s += v[t]; }
    #pragma unroll
    for (int o = 16; o; o >>= 1) s += __shfl_xor_sync(~0u, s, o);
    if ((tid & 31) == 0) red[tid >> 5] = s;
    __syncthreads();
    s = 0.f;
    #pragma unroll
    for (int w = 0; w < 8; w++) s += red[w];
    const float mu = s * (1.0f / DD);
    __syncthreads();

    float var = 0.f;
    #pragma unroll
    for (int t = 0; t < 3; t++) { float d = v[t] - mu; var += d * d; }
    #pragma unroll
    for (int o = 16; o; o >>= 1) var += __shfl_xor_sync(~0u, var, o);
    if ((tid & 31) == 0) red[tid >> 5] = var;
    __syncthreads();
    var = 0.f;
    #pragma unroll
    for (int w = 0; w < 8; w++) var += red[w];
    const float inv = rsqrtf(var * (1.0f / DD) + 1e-5f);

    #pragma unroll
    for (int t = 0; t < 3; t++) {
        int c = tid + t * 256;
        out[row * DD + c] = (v[t] - mu) * inv * lg[c] + lb[c];
    }
}

// ---------------------------------------------------------------------------
extern "C" void kernel_launch(void* const* d_in, const int* in_sizes, int n_in,
                              void* d_out, int out_size)
{
    const float* Q  = (const float*)d_in[0];
    const float* K  = (const float*)d_in[1];
    const float* V  = (const float*)d_in[2];
    const int*   pad = (const int*)d_in[3];
    const float* Wq = (const float*)d_in[4];
    const float* bq = (const float*)d_in[5];
    const float* Wk = (const float*)d_in[6];
    const float* bk = (const float*)d_in[7];
    const float* Wv = (const float*)d_in[8];
    const float* bv = (const float*)d_in[9];
    const float* Wo = (const float*)d_in[10];
    const float* bo = (const float*)d_in[11];
    const float* lg = (const float*)d_in[12];
    const float* lb = (const float*)d_in[13];
    float* out = (float*)d_out;

    float* attn = ((long long)out_size >= OUT_ELEMS + ATTN_ELEMS) ? (out + OUT_ELEMS)
                                                                  : nullptr;

    const int GEMM_SMEM   = 26112 * 4;   // 104448
    const int SCORES_SMEM = 17408 * 4;   // 69632
    const int CTX_SMEM    = 26240 * 4;   // 104960
    cudaFuncSetAttribute(qkv_kernel, cudaFuncAttributeMaxDynamicSharedMemorySize, GEMM_SMEM);
    cudaFuncSetAttribute(outproj_kernel, cudaFuncAttributeMaxDynamicSharedMemorySize, GEMM_SMEM);
    cudaFuncSetAttribute(scores_kernel, cudaFuncAttributeMaxDynamicSharedMemorySize, SCORES_SMEM);
    cudaFuncSetAttribute(context_kernel, cudaFuncAttributeMaxDynamicSharedMemorySize, CTX_SMEM);

    maskpack_kernel<<<(BB * SS * (SS / 32)) / 256, 256>>>(pad);
    wtrans_kernel<<<dim3(24, 24, 4), 256>>>(Wq, Wk, Wv, Wo);
    roundperm_kernel<<<dim3((BB * SS * DD / 8) / 256, 3), 256>>>(Q, K, V);

    dim3 gq(DD / 64, (BB * SS) / 128, 3);       // (12, 64, 3)
    qkv_kernel<<<gq, 256, GEMM_SMEM>>>(bq, bk, bv);

    dim3 gs(SS / 128, SS / 128, BB * HH);       // (16, 16, 48)
    scores_kernel<<<gs, 256, SCORES_SMEM>>>(attn);

    rowinv_kernel<<<(BB * HH * SS) / 256, 256>>>();

    dim3 gc(SS / 128, BB * HH);                 // (16, 48)
    context_kernel<<<gc, 256, CTX_SMEM>>>(attn);

    dim3 gp(DD / 64, (BB * SS) / 128);          // (12, 64)
    outproj_kernel<<<gp, 256, GEMM_SMEM>>>(bo, Q);

    ln_kernel<<<BB * SS, 256>>>(lg, lb, out);
}

// round 12
// speedup vs baseline: 1.2582x; 1.0856x over previous
#include <cuda_runtime.h>
#include <cstdint>
#include <math.h>

#define BB 4
#define SS 2048
#define DD 768
#define HH 12
#define DKK 64

typedef unsigned long long ull;

static const long long OUT_ELEMS  = (long long)BB * SS * DD;
static const long long ATTN_ELEMS = (long long)BB * HH * SS * SS;

// octet permutation: logical k -> physical slot (within groups of 8)
#define PHYS8(k) (((k) & ~7) | (((k) & 3) << 1) | (((k) >> 2) & 1))

// Scratch
__device__ float g_q[BB * HH * SS * DKK];     // rounded + k-permuted
__device__ float g_k[BB * HH * SS * DKK];     // rounded + k-permuted
__device__ float g_v[BB * HH * SS * DKK];     // rounded, plain layout
__device__ float g_ctx[BB * SS * DD];         // rounded + k-permuted
__device__ float g_pre[BB * SS * DD];
__device__ float g_psum[(size_t)BB * HH * SS * 32];
__device__ float g_rowinv[(size_t)BB * HH * SS];
__device__ uint32_t g_maskbits[(size_t)BB * SS * (SS / 32)];
__device__ float g_attn_fb[(long long)BB * HH * SS * SS];
__device__ float g_wTp[4][DD * DD];           // [n][k] transposed, rounded, permuted
__device__ float g_xr[3][BB * SS * DD];       // rounded + permuted Q/K/V inputs

__device__ __forceinline__ uint32_t cvt_tf32(float x) {
    uint32_t u; asm("cvt.rna.tf32.f32 %0, %1;" : "=r"(u) : "f"(x)); return u;
}
__device__ __forceinline__ float rnd(float x) { return __uint_as_float(cvt_tf32(x)); }

__device__ __forceinline__ void mma8(float* c, const uint32_t* a, const uint32_t* b) {
    asm("mma.sync.aligned.m16n8k8.row.col.f32.tf32.tf32.f32 "
        "{%0,%1,%2,%3},{%4,%5,%6,%7},{%8,%9},{%0,%1,%2,%3};"
        : "+f"(c[0]), "+f"(c[1]), "+f"(c[2]), "+f"(c[3])
        : "r"(a[0]), "r"(a[1]), "r"(a[2]), "r"(a[3]), "r"(b[0]), "r"(b[1]));
}

__device__ __forceinline__ void cp16(uint32_t dst, const void* src) {
    asm volatile("cp.async.cg.shared.global [%0], [%1], 16;" :: "r"(dst), "l"(src));
}
__device__ __forceinline__ void cp_commit() { asm volatile("cp.async.commit_group;"); }
template<int N> __device__ __forceinline__ void cp_wait() {
    asm volatile("cp.async.wait_group %0;" :: "n"(N));
}

// ---------------------------------------------------------------------------
// Mask bit-pack: int32 [4,2048,2048] -> bitmask. bit=1 -> masked.
// ---------------------------------------------------------------------------
__global__ void __launch_bounds__(256) maskpack_kernel(const int* __restrict__ pad)
{
    size_t w = (size_t)blockIdx.x * 256 + threadIdx.x;
    const int4* p = reinterpret_cast<const int4*>(pad + w * 32);
    uint32_t bits = 0;
    #pragma unroll
    for (int t = 0; t < 8; t++) {
        int4 v = p[t];
        bits |= (uint32_t)(v.x != 0) << (4 * t);
        bits |= (uint32_t)(v.y != 0) << (4 * t + 1);
        bits |= (uint32_t)(v.z != 0) << (4 * t + 2);
        bits |= (uint32_t)(v.w != 0) << (4 * t + 3);
    }
    g_maskbits[w] = bits;
}

// ---------------------------------------------------------------------------
// Weight transpose + round + k-permute: g_wTp[z][n*DD + PHYS8(k)] = rna(W[k][n]).
// ---------------------------------------------------------------------------
__global__ void __launch_bounds__(256) wtrans_kernel(
    const float* __restrict__ Wq, const float* __restrict__ Wk,
    const float* __restrict__ Wv, const float* __restrict__ Wo)
{
    const float* W = (blockIdx.z == 0) ? Wq : (blockIdx.z == 1) ? Wk
                   : (blockIdx.z == 2) ? Wv : Wo;
    float* T = g_wTp[blockIdx.z];
    __shared__ float tile[32][33];
    int k0 = blockIdx.y * 32, n0 = blockIdx.x * 32;
    int tx = threadIdx.x & 31, ty = threadIdx.x >> 5;
    #pragma unroll
    for (int i = 0; i < 4; i++)
        tile[ty + i * 8][tx] = W[(size_t)(k0 + ty + i * 8) * DD + n0 + tx];
    __syncthreads();
    #pragma unroll
    for (int i = 0; i < 4; i++)
        T[(size_t)(n0 + ty + i * 8) * DD + k0 + PHYS8(tx)] = rnd(tile[tx][ty + i * 8]);
}

// ---------------------------------------------------------------------------
// Round + permute X inputs: one thread per octet; stores stay float4.
// ---------------------------------------------------------------------------
__global__ void __launch_bounds__(256) roundperm_kernel(
    const float* __restrict__ Q, const float* __restrict__ K, const float* __restrict__ V)
{
    const float* X = (blockIdx.y == 0) ? Q : (blockIdx.y == 1) ? K : V;
    float* O = g_xr[blockIdx.y];
    size_t o = (size_t)blockIdx.x * 256 + threadIdx.x;   // octet index
    const float4* p = reinterpret_cast<const float4*>(X) + o * 2;
    float4 lo = p[0], hi = p[1];
    float4 o0 = make_float4(rnd(lo.x), rnd(hi.x), rnd(lo.y), rnd(hi.y));
    float4 o1 = make_float4(rnd(lo.z), rnd(hi.z), rnd(lo.w), rnd(hi.w));
    float4* q = reinterpret_cast<float4*>(O) + o * 2;
    q[0] = o0; q[1] = o1;
}

// ---------------------------------------------------------------------------
// QKV projection (merged): Y = X @ W + bias, [B,H,S,DK] layout.
// 128 threads, warps 2x2, warp tile 64x32 (16 MMAs / 12 LDS.64 per kk-step).
// ---------------------------------------------------------------------------
__global__ void __launch_bounds__(128) qkv_kernel(
    const float* __restrict__ bq, const float* __restrict__ bk, const float* __restrict__ bv)
{
    const int z = blockIdx.z;
    const float* X = g_xr[z];
    const float* W = g_wTp[z];
    const float* bias = (z == 0) ? bq : (z == 1) ? bk : bv;
    float* Y = (z == 0) ? g_q : (z == 1) ? g_k : g_v;

    extern __shared__ float smf[];
    const uint32_t smb = (uint32_t)__cvta_generic_to_shared(smf);

    const int tid = threadIdx.x, wid = tid >> 5, lane = tid & 31;
    const int gid = lane >> 2, tig = lane & 3;
    const int m0 = blockIdx.y * 128, n0 = blockIdx.x * 64;
    const int wm = (wid >> 1) * 64, wn = (wid & 1) * 32;

    float acc[4][4][4] = {};

    #define XS(s,r,c) smf[(s)*8704 + (r)*68 + (c)]
    #define WS(s,r,c) smf[17408 + (s)*4352 + (r)*68 + (c)]   // [n][k]
    auto load_chunk = [&](int s, int k0) {
        #pragma unroll
        for (int t = 0; t < 16; t++) {
            int idx = tid + t * 128, r = idx >> 4, g = idx & 15;
            cp16(smb + (uint32_t)((s * 8704 + r * 68 + g * 4) * 4),
                 X + (size_t)(m0 + r) * DD + k0 + g * 4);
        }
        #pragma unroll
        for (int t = 0; t < 8; t++) {
            int idx = tid + t * 128, r = idx >> 4, g = idx & 15;
            cp16(smb + (uint32_t)((17408 + s * 4352 + r * 68 + g * 4) * 4),
                 W + (size_t)(n0 + r) * DD + k0 + g * 4);
        }
        cp_commit();
    };

    load_chunk(0, 0);
    for (int it = 0; it < 12; it++) {
        if (it + 1 < 12) { load_chunk((it + 1) & 1, (it + 1) * 64); cp_wait<1>(); }
        else cp_wait<0>();
        __syncthreads();
        const int s = it & 1;
        #pragma unroll
        for (int kk = 0; kk < 64; kk += 8) {
            uint32_t a[4][4], b[4][2];
            #pragma unroll
            for (int mi = 0; mi < 4; mi++) {
                int r = wm + mi * 16 + gid;
                uint2 la = *reinterpret_cast<const uint2*>(&XS(s, r, kk + 2 * tig));
                uint2 lb = *reinterpret_cast<const uint2*>(&XS(s, r + 8, kk + 2 * tig));
                a[mi][0] = la.x; a[mi][1] = lb.x; a[mi][2] = la.y; a[mi][3] = lb.y;
            }
            #pragma unroll
            for (int nj = 0; nj < 4; nj++) {
                int n = wn + nj * 8 + gid;
                uint2 w2 = *reinterpret_cast<const uint2*>(&WS(s, n, kk + 2 * tig));
                b[nj][0] = w2.x; b[nj][1] = w2.y;
            }
            #pragma unroll
            for (int mi = 0; mi < 4; mi++)
                #pragma unroll
                for (int nj = 0; nj < 4; nj++) mma8(acc[mi][nj], a[mi], b[nj]);
        }
        __syncthreads();
    }
    #undef XS
    #undef WS

    #pragma unroll
    for (int mi = 0; mi < 4; mi++)
        #pragma unroll
        for (int rr = 0; rr < 2; rr++) {
            int r = m0 + wm + mi * 16 + gid + rr * 8;
            int b_ = r >> 11, sidx = r & 2047;
            #pragma unroll
            for (int nj = 0; nj < 4; nj++) {
                int c = n0 + wn + nj * 8 + tig * 2;
                float v0 = rnd(acc[mi][nj][rr * 2 + 0] + bias[c]);
                float v1 = rnd(acc[mi][nj][rr * 2 + 1] + bias[c + 1]);
                int h = c >> 6, d = c & 63;
                float* o = Y + (((size_t)b_ * HH + h) * SS + sidx) * DKK;
                if (z == 2) {
                    *reinterpret_cast<float2*>(o + d) = make_float2(v0, v1);
                } else {
                    o[PHYS8(d)] = v0;
                    o[PHYS8(d + 1)] = v1;
                }
            }
        }
}

// ---------------------------------------------------------------------------
// Scores+exp: unchanged from R11.
// ---------------------------------------------------------------------------
__global__ void __launch_bounds__(256) scores_kernel(float* __restrict__ attn_ext)
{
    float* attn = attn_ext ? attn_ext : g_attn_fb;
    extern __shared__ uint32_t smu[];
    uint32_t (*Qs)[68] = reinterpret_cast<uint32_t(*)[68]>(smu);
    uint32_t (*Ks)[68] = reinterpret_cast<uint32_t(*)[68]>(smu + 128 * 68);
    float (*Ss)[132]   = reinterpret_cast<float(*)[132]>(smu);

    const int bh = blockIdx.z, b_ = bh / HH;
    const int q0 = blockIdx.y * 128, k0 = blockIdx.x * 128;
    const int tid = threadIdx.x, wid = tid >> 5, lane = tid & 31;
    const int gid = lane >> 2, tig = lane & 3;
    const int wm = (wid >> 1) * 32, wn = (wid & 1) * 64;

    const float* qp = g_q + ((size_t)bh * SS + q0) * DKK;
    const float* kp = g_k + ((size_t)bh * SS + k0) * DKK;

    #pragma unroll
    for (int t = 0; t < 8; t++) {
        int e = (tid + t * 256) * 4, r = e >> 6, c = e & 63;
        *reinterpret_cast<uint4*>(&Qs[r][c]) =
            *reinterpret_cast<const uint4*>(qp + (size_t)r * DKK + c);
        *reinterpret_cast<uint4*>(&Ks[r][c]) =
            *reinterpret_cast<const uint4*>(kp + (size_t)r * DKK + c);
    }
    __syncthreads();

    float acc[2][8][4] = {};
    #pragma unroll
    for (int kk = 0; kk < 64; kk += 8) {
        uint32_t a[2][4], b[8][2];
        #pragma unroll
        for (int mi = 0; mi < 2; mi++) {
            int r = wm + mi * 16 + gid;
            uint2 la = *reinterpret_cast<const uint2*>(&Qs[r][kk + 2 * tig]);
            uint2 lb = *reinterpret_cast<const uint2*>(&Qs[r + 8][kk + 2 * tig]);
            a[mi][0] = la.x; a[mi][1] = lb.x; a[mi][2] = la.y; a[mi][3] = lb.y;
        }
        #pragma unroll
        for (int nj = 0; nj < 8; nj++) {
            int n = wn + nj * 8 + gid;
            uint2 kb = *reinterpret_cast<const uint2*>(&Ks[n][kk + 2 * tig]);
            b[nj][0] = kb.x; b[nj][1] = kb.y;
        }
        #pragma unroll
        for (int mi = 0; mi < 2; mi++)
            #pragma unroll
            for (int nj = 0; nj < 8; nj++) mma8(acc[mi][nj], a[mi], b[nj]);
    }
    __syncthreads();

    #pragma unroll
    for (int mi = 0; mi < 2; mi++)
        #pragma unroll
        for (int rr = 0; rr < 2; rr++) {
            int qrl = wm + mi * 16 + gid + rr * 8;
            int qr = q0 + qrl;
            uint2 mw = *reinterpret_cast<const uint2*>(
                g_maskbits + ((size_t)b_ * SS + qr) * (SS / 32) + (k0 + wn) / 32);
            ull m64 = (ull)mw.x | ((ull)mw.y << 32);
            float rs = 0.f;
            #pragma unroll
            for (int nj = 0; nj < 8; nj++) {
                int j = nj * 8 + tig * 2;
                float v0 = acc[mi][nj][rr * 2 + 0] * 0.125f;
                float v1 = acc[mi][nj][rr * 2 + 1] * 0.125f;
                float p0 = ((m64 >> j) & 1ull) ? 0.f : __expf(v0);
                float p1 = ((m64 >> (j + 1)) & 1ull) ? 0.f : __expf(v1);
                rs += p0 + p1;
                *reinterpret_cast<float2*>(&Ss[qrl][wn + j]) = make_float2(p0, p1);
            }
            rs += __shfl_xor_sync(~0u, rs, 1);
            rs += __shfl_xor_sync(~0u, rs, 2);
            if (tig == 0)
                g_psum[((size_t)bh * SS + qr) * 32 + blockIdx.x * 2 + (wid & 1)] = rs;
        }
    __syncthreads();

    const size_t base = (size_t)bh * SS * SS;
    #pragma unroll
    for (int t = 0; t < 16; t++) {
        int idx = tid + t * 256;
        int r = idx >> 5, c4 = (idx & 31) * 4;
        float4 v = *reinterpret_cast<const float4*>(&Ss[r][c4]);
        *reinterpret_cast<float4*>(attn + base + (size_t)(q0 + r) * SS + k0 + c4) = v;
    }
}

// ---------------------------------------------------------------------------
__global__ void __launch_bounds__(256) rowinv_kernel()
{
    size_t idx = (size_t)blockIdx.x * 256 + threadIdx.x;
    const float4* p = reinterpret_cast<const float4*>(g_psum + idx * 32);
    float s = 0.f;
    #pragma unroll
    for (int t = 0; t < 8; t++) { float4 v = p[t]; s += v.x + v.y + v.z + v.w; }
    g_rowinv[idx] = 1.0f / s;
}

// ---------------------------------------------------------------------------
// Context: 128 threads, warps 2x2, warp tile 64x32.
// Normalize exp on load (write final attn), MMA with V (pre-rounded).
// ---------------------------------------------------------------------------
__global__ void __launch_bounds__(128) context_kernel(float* __restrict__ attn_ext)
{
    float* attn = attn_ext ? attn_ext : g_attn_fb;
    extern __shared__ float smf[];
    const uint32_t smb = (uint32_t)__cvta_generic_to_shared(smf);
    float* invs = smf + 26112;

    const int bh = blockIdx.y, q0 = blockIdx.x * 128;
    const int tid = threadIdx.x, wid = tid >> 5, lane = tid & 31;
    const int gid = lane >> 2, tig = lane & 3;
    const int wm = (wid >> 1) * 64, wn = (wid & 1) * 32;

    float* ap = attn + ((size_t)bh * SS + q0) * SS;
    const float* vp = g_v + (size_t)bh * SS * DKK;

    invs[tid] = g_rowinv[(size_t)bh * SS + q0 + tid];

    #define AS(s,r,c) smf[(s)*8704 + (r)*68 + (c)]
    #define VS(s,r,c) smf[17408 + (s)*4352 + (r)*68 + (c)]
    auto load_chunk = [&](int s, int k0) {
        #pragma unroll
        for (int t = 0; t < 16; t++) {
            int e = (tid + t * 128) * 4, r = e >> 6, c = e & 63;
            cp16(smb + (uint32_t)((s * 8704 + r * 68 + c) * 4),
                 ap + (size_t)r * SS + k0 + c);
        }
        #pragma unroll
        for (int t = 0; t < 8; t++) {
            int e = (tid + t * 128) * 4, r = e >> 6, c = e & 63;
            cp16(smb + (uint32_t)((17408 + s * 4352 + r * 68 + c) * 4),
                 vp + (size_t)(k0 + r) * DKK + c);
        }
        cp_commit();
    };

    float acc[4][4][4] = {};
    load_chunk(0, 0);
    for (int it = 0; it < 32; it++) {
        if (it + 1 < 32) { load_chunk((it + 1) & 1, (it + 1) * 64); cp_wait<1>(); }
        else cp_wait<0>();
        __syncthreads();
        const int s = it & 1;
        const int k0 = it * 64;

        // normalize + global writeback + tf32-cvt in place (attn only)
        #pragma unroll
        for (int t = 0; t < 16; t++) {
            int e = (tid + t * 128) * 4, r = e >> 6, c = e & 63;
            float4 v = *reinterpret_cast<const float4*>(&AS(s, r, c));
            float inv = invs[r];
            v.x *= inv; v.y *= inv; v.z *= inv; v.w *= inv;
            *reinterpret_cast<float4*>(ap + (size_t)r * SS + k0 + c) = v;
            uint32_t* u = reinterpret_cast<uint32_t*>(&AS(s, r, c));
            u[0] = cvt_tf32(v.x); u[1] = cvt_tf32(v.y);
            u[2] = cvt_tf32(v.z); u[3] = cvt_tf32(v.w);
        }
        __syncthreads();

        #pragma unroll
        for (int kk = 0; kk < 64; kk += 8) {
            uint32_t a[4][4], b[4][2];
            #pragma unroll
            for (int mi = 0; mi < 4; mi++) {
                int r = wm + mi * 16 + gid;
                a[mi][0] = __float_as_uint(AS(s, r, kk + tig));
                a[mi][1] = __float_as_uint(AS(s, r + 8, kk + tig));
                a[mi][2] = __float_as_uint(AS(s, r, kk + tig + 4));
                a[mi][3] = __float_as_uint(AS(s, r + 8, kk + tig + 4));
            }
            #pragma unroll
            for (int nj = 0; nj < 4; nj++) {
                int n = wn + nj * 8 + gid;
                b[nj][0] = __float_as_uint(VS(s, kk + tig, n));
                b[nj][1] = __float_as_uint(VS(s, kk + tig + 4, n));
            }
            #pragma unroll
            for (int mi = 0; mi < 4; mi++)
                #pragma unroll
                for (int nj = 0; nj < 4; nj++) mma8(acc[mi][nj], a[mi], b[nj]);
        }
        __syncthreads();
    }
    #undef AS
    #undef VS

    const int b_ = bh / HH, h = bh % HH;
    #pragma unroll
    for (int mi = 0; mi < 4; mi++)
        #pragma unroll
        for (int rr = 0; rr < 2; rr++) {
            int s = q0 + wm + mi * 16 + gid + rr * 8;
            #pragma unroll
            for (int nj = 0; nj < 4; nj++) {
                int d = wn + nj * 8 + tig * 2;
                float r0 = rnd(acc[mi][nj][rr * 2]);
                float r1 = rnd(acc[mi][nj][rr * 2 + 1]);
                float* o = &g_ctx[((size_t)b_ * SS + s) * DD + h * DKK];
                o[PHYS8(d)] = r0;
                o[PHYS8(d + 1)] = r1;
            }
        }
}

// ---------------------------------------------------------------------------
// Output projection: 128 threads, warps 2x2, warp tile 64x32.
// ---------------------------------------------------------------------------
__global__ void __launch_bounds__(128) outproj_kernel(
    const float* __restrict__ bias, const float* __restrict__ resid)
{
    const float* X = g_ctx;
    const float* W = g_wTp[3];
    extern __shared__ float smf[];
    const uint32_t smb = (uint32_t)__cvta_generic_to_shared(smf);

    const int tid = threadIdx.x, wid = tid >> 5, lane = tid & 31;
    const int gid = lane >> 2, tig = lane & 3;
    const int m0 = blockIdx.y * 128, n0 = blockIdx.x * 64;
    const int wm = (wid >> 1) * 64, wn = (wid & 1) * 32;

    float acc[4][4][4] = {};

    #define XS(s,r,c) smf[(s)*8704 + (r)*68 + (c)]
    #define WS(s,r,c) smf[17408 + (s)*4352 + (r)*68 + (c)]
    auto load_chunk = [&](int s, int k0) {
        #pragma unroll
        for (int t = 0; t < 16; t++) {
            int idx = tid + t * 128, r = idx >> 4, g = idx & 15;
            cp16(smb + (uint32_t)((s * 8704 + r * 68 + g * 4) * 4),
                 X + (size_t)(m0 + r) * DD + k0 + g * 4);
        }
        #pragma unroll
        for (int t = 0; t < 8; t++) {
            int idx = tid + t * 128, r = idx >> 4, g = idx & 15;
            cp16(smb + (uint32_t)((17408 + s * 4352 + r * 68 + g * 4) * 4),
                 W + (size_t)(n0 + r) * DD + k0 + g * 4);
        }
        cp_commit();
    };

    load_chunk(0, 0);
    for (int it = 0; it < 12; it++) {
        if (it + 1 < 12) { load_chunk((it + 1) & 1, (it + 1) * 64); cp_wait<1>(); }
        else cp_wait<0>();
        __syncthreads();
        const int s = it & 1;
        #pragma unroll
        for (int kk = 0; kk < 64; kk += 8) {
            uint32_t a[4][4], b[4][2];
            #pragma unroll
            for (int mi = 0; mi < 4; mi++) {
                int r = wm + mi * 16 + gid;
                uint2 la = *reinterpret_cast<const uint2*>(&XS(s, r, kk + 2 * tig));
                uint2 lb = *reinterpret_cast<const uint2*>(&XS(s, r + 8, kk + 2 * tig));
                a[mi][0] = la.x; a[mi][1] = lb.x; a[mi][2] = la.y; a[mi][3] = lb.y;
            }
            #pragma unroll
            for (int nj = 0; nj < 4; nj++) {
                int n = wn + nj * 8 + gid;
                uint2 w2 = *reinterpret_cast<const uint2*>(&WS(s, n, kk + 2 * tig));
                b[nj][0] = w2.x; b[nj][1] = w2.y;
            }
            #pragma unroll
            for (int mi = 0; mi < 4; mi++)
                #pragma unroll
                for (int nj = 0; nj < 4; nj++) mma8(acc[mi][nj], a[mi], b[nj]);
        }
        __syncthreads();
    }
    #undef XS
    #undef WS

    #pragma unroll
    for (int mi = 0; mi < 4; mi++)
        #pragma unroll
        for (int rr = 0; rr < 2; rr++) {
            int r = m0 + wm + mi * 16 + gid + rr * 8;
            #pragma unroll
            for (int nj = 0; nj < 4; nj++) {
                int c = n0 + wn + nj * 8 + tig * 2;
                float v0 = acc[mi][nj][rr * 2 + 0] + bias[c];
                float v1 = acc[mi][nj][rr * 2 + 1] + bias[c + 1];
                const float2 rs = *reinterpret_cast<const float2*>(&resid[(size_t)r * DD + c]);
                *reinterpret_cast<float2*>(&g_pre[(size_t)r * DD + c]) =
                    make_float2(v0 + rs.x, v1 + rs.y);
            }
        }
}

// ---------------------------------------------------------------------------
// LayerNorm over D=768.
// ---------------------------------------------------------------------------
__global__ void __launch_bounds__(256) ln_kernel(
    const float* __restrict__ lg, const float* __restrict__ lb, float* __restrict__ out)
{
    const size_t row = blockIdx.x;
    const float* x = g_pre + row * DD;
    const int tid = threadIdx.x;
    __shared__ float red[8];

    float v[3];
    float s = 0.f;
    #pragma unroll
    for (int t = 0; t < 3; t++) { v[t] = x[tid + t * 256]; s += v[t]; }
    #pragma unroll
    for (int o = 16; o; o >>= 1) s += __shfl_xor_sync(~0u, s, o);
    if ((tid & 31) == 0) red[tid >> 5] = s;
    __syncthreads();
    s = 0.f;
    #pragma unroll
    for (int w = 0; w < 8; w++) s += red[w];
    const float mu = s * (1.0f / DD);
    __syncthreads();

    float var = 0.f;
    #pragma unroll
    for (int t = 0; t < 3; t++) { float d = v[t] - mu; var += d * d; }
    #pragma unroll
    for (int o = 16; o; o >>= 1) var += __shfl_xor_sync(~0u, var, o);
    if ((tid & 31) == 0) red[tid >> 5] = var;
    __syncthreads();
    var = 0.f;
    #pragma unroll
    for (int w = 0; w < 8; w++) var += red[w];
    const float inv = rsqrtf(var * (1.0f / DD) + 1e-5f);

    #pragma unroll
    for (int t = 0; t < 3; t++) {
        int c = tid + t * 256;
        out[row * DD + c] = (v[t] - mu) * inv * lg[c] + lb[c];
    }
}

// ---------------------------------------------------------------------------
extern "C" void kernel_launch(void* const* d_in, const int* in_sizes, int n_in,
                              void* d_out, int out_size)
{
    const float* Q  = (const float*)d_in[0];
    const float* K  = (const float*)d_in[1];
    const float* V  = (const float*)d_in[2];
    const int*   pad = (const int*)d_in[3];
    const float* Wq = (const float*)d_in[4];
    const float* bq = (const float*)d_in[5];
    const float* Wk = (const float*)d_in[6];
    const float* bk = (const float*)d_in[7];
    const float* Wv = (const float*)d_in[8];
    const float* bv = (const float*)d_in[9];
    const float* Wo = (const float*)d_in[10];
    const float* bo = (const float*)d_in[11];
    const float* lg = (const float*)d_in[12];
    const float* lb = (const float*)d_in[13];
    float* out = (float*)d_out;

    float* attn = ((long long)out_size >= OUT_ELEMS + ATTN_ELEMS) ? (out + OUT_ELEMS)
                                                                  : nullptr;

    const int GEMM_SMEM   = 26112 * 4;   // 104448
    const int SCORES_SMEM = 17408 * 4;   // 69632
    const int CTX_SMEM    = 26240 * 4;   // 104960
    cudaFuncSetAttribute(qkv_kernel, cudaFuncAttributeMaxDynamicSharedMemorySize, GEMM_SMEM);
    cudaFuncSetAttribute(outproj_kernel, cudaFuncAttributeMaxDynamicSharedMemorySize, GEMM_SMEM);
    cudaFuncSetAttribute(scores_kernel, cudaFuncAttributeMaxDynamicSharedMemorySize, SCORES_SMEM);
    cudaFuncSetAttribute(context_kernel, cudaFuncAttributeMaxDynamicSharedMemorySize, CTX_SMEM);

    maskpack_kernel<<<(BB * SS * (SS / 32)) / 256, 256>>>(pad);
    wtrans_kernel<<<dim3(24, 24, 4), 256>>>(Wq, Wk, Wv, Wo);
    roundperm_kernel<<<dim3((BB * SS * DD / 8) / 256, 3), 256>>>(Q, K, V);

    dim3 gq(DD / 64, (BB * SS) / 128, 3);       // (12, 64, 3)
    qkv_kernel<<<gq, 128, GEMM_SMEM>>>(bq, bk, bv);

    dim3 gs(SS / 128, SS / 128, BB * HH);       // (16, 16, 48)
    scores_kernel<<<gs, 256, SCORES_SMEM>>>(attn);

    rowinv_kernel<<<(BB * HH * SS) / 256, 256>>>();

    dim3 gc(SS / 128, BB * HH);                 // (16, 48)
    context_kernel<<<gc, 128, CTX_SMEM>>>(attn);

    dim3 gp(DD / 64, (BB * SS) / 128);          // (12, 64)
    outproj_kernel<<<gp, 128, GEMM_SMEM>>>(bo, Q);

    ln_kernel<<<BB * SS, 256>>>(lg, lb, out);
}

// round 14
// speedup vs baseline: 1.2928x; 1.0275x over previous
#include <cuda_runtime.h>
#include <cstdint>
#include <math.h>

#define BB 4
#define SS 2048
#define DD 768
#define HH 12
#define DKK 64

typedef unsigned long long ull;

static const long long OUT_ELEMS  = (long long)BB * SS * DD;
static const long long ATTN_ELEMS = (long long)BB * HH * SS * SS;

// octet permutation: logical k -> physical slot (within groups of 8)
#define PHYS8(k) (((k) & ~7) | (((k) & 3) << 1) | (((k) >> 2) & 1))

// Scratch
__device__ float g_q[BB * HH * SS * DKK];     // rounded + k-permuted
__device__ float g_k[BB * HH * SS * DKK];     // rounded + k-permuted
__device__ float g_v[BB * HH * SS * DKK];     // rounded, plain layout
__device__ float g_ctx[BB * SS * DD];         // rounded + k-permuted
__device__ float g_pre[BB * SS * DD];
__device__ float g_psum[(size_t)BB * HH * SS * 32];
__device__ float g_rowinv[(size_t)BB * HH * SS];
__device__ uint32_t g_maskbits[(size_t)BB * SS * (SS / 32)];
__device__ float g_attn_fb[(long long)BB * HH * SS * SS];
__device__ float g_wTp[4][DD * DD];           // [n][k] transposed, rounded, permuted
__device__ float g_xr[3][BB * SS * DD];       // rounded + permuted Q/K/V inputs

__device__ __forceinline__ uint32_t cvt_tf32(float x) {
    uint32_t u; asm("cvt.rna.tf32.f32 %0, %1;" : "=r"(u) : "f"(x)); return u;
}
__device__ __forceinline__ float rnd(float x) { return __uint_as_float(cvt_tf32(x)); }

__device__ __forceinline__ void mma8(float* c, const uint32_t* a, const uint32_t* b) {
    asm("mma.sync.aligned.m16n8k8.row.col.f32.tf32.tf32.f32 "
        "{%0,%1,%2,%3},{%4,%5,%6,%7},{%8,%9},{%0,%1,%2,%3};"
        : "+f"(c[0]), "+f"(c[1]), "+f"(c[2]), "+f"(c[3])
        : "r"(a[0]), "r"(a[1]), "r"(a[2]), "r"(a[3]), "r"(b[0]), "r"(b[1]));
}

__device__ __forceinline__ void cp16(uint32_t dst, const void* src) {
    asm volatile("cp.async.cg.shared.global [%0], [%1], 16;" :: "r"(dst), "l"(src));
}
__device__ __forceinline__ void cp_commit() { asm volatile("cp.async.commit_group;"); }
template<int N> __device__ __forceinline__ void cp_wait() {
    asm volatile("cp.async.wait_group %0;" :: "n"(N));
}

// ---------------------------------------------------------------------------
// Mask bit-pack: int32 [4,2048,2048] -> bitmask. bit=1 -> masked.
// ---------------------------------------------------------------------------
__global__ void __launch_bounds__(256) maskpack_kernel(const int* __restrict__ pad)
{
    size_t w = (size_t)blockIdx.x * 256 + threadIdx.x;
    const int4* p = reinterpret_cast<const int4*>(pad + w * 32);
    uint32_t bits = 0;
    #pragma unroll
    for (int t = 0; t < 8; t++) {
        int4 v = p[t];
        bits |= (uint32_t)(v.x != 0) << (4 * t);
        bits |= (uint32_t)(v.y != 0) << (4 * t + 1);
        bits |= (uint32_t)(v.z != 0) << (4 * t + 2);
        bits |= (uint32_t)(v.w != 0) << (4 * t + 3);
    }
    g_maskbits[w] = bits;
}

// ---------------------------------------------------------------------------
// Weight transpose + round + k-permute: g_wTp[z][n*DD + PHYS8(k)] = rna(W[k][n]).
// ---------------------------------------------------------------------------
__global__ void __launch_bounds__(256) wtrans_kernel(
    const float* __restrict__ Wq, const float* __restrict__ Wk,
    const float* __restrict__ Wv, const float* __restrict__ Wo)
{
    const float* W = (blockIdx.z == 0) ? Wq : (blockIdx.z == 1) ? Wk
                   : (blockIdx.z == 2) ? Wv : Wo;
    float* T = g_wTp[blockIdx.z];
    __shared__ float tile[32][33];
    int k0 = blockIdx.y * 32, n0 = blockIdx.x * 32;
    int tx = threadIdx.x & 31, ty = threadIdx.x >> 5;
    #pragma unroll
    for (int i = 0; i < 4; i++)
        tile[ty + i * 8][tx] = W[(size_t)(k0 + ty + i * 8) * DD + n0 + tx];
    __syncthreads();
    #pragma unroll
    for (int i = 0; i < 4; i++)
        T[(size_t)(n0 + ty + i * 8) * DD + k0 + PHYS8(tx)] = rnd(tile[tx][ty + i * 8]);
}

// ---------------------------------------------------------------------------
// Round + permute X inputs: one thread per octet; stores stay float4.
// ---------------------------------------------------------------------------
__global__ void __launch_bounds__(256) roundperm_kernel(
    const float* __restrict__ Q, const float* __restrict__ K, const float* __restrict__ V)
{
    const float* X = (blockIdx.y == 0) ? Q : (blockIdx.y == 1) ? K : V;
    float* O = g_xr[blockIdx.y];
    size_t o = (size_t)blockIdx.x * 256 + threadIdx.x;   // octet index
    const float4* p = reinterpret_cast<const float4*>(X) + o * 2;
    float4 lo = p[0], hi = p[1];
    float4 o0 = make_float4(rnd(lo.x), rnd(hi.x), rnd(lo.y), rnd(hi.y));
    float4 o1 = make_float4(rnd(lo.z), rnd(hi.z), rnd(lo.w), rnd(hi.w));
    float4* q = reinterpret_cast<float4*>(O) + o * 2;
    q[0] = o0; q[1] = o1;
}

// ---------------------------------------------------------------------------
// QKV projection (merged): Y = X @ W + bias, [B,H,S,DK] layout.
// 128 threads, warps 2x2, warp tile 64x32. BK=32, 2-stage, 3 CTAs/SM.
// smem floats: Xs s*4608 [128][36]; Ws 9216 + s*2304 [64][36] (n-major).
// ---------------------------------------------------------------------------
__global__ void __launch_bounds__(128, 3) qkv_kernel(
    const float* __restrict__ bq, const float* __restrict__ bk, const float* __restrict__ bv)
{
    const int z = blockIdx.z;
    const float* X = g_xr[z];
    const float* W = g_wTp[z];
    const float* bias = (z == 0) ? bq : (z == 1) ? bk : bv;
    float* Y = (z == 0) ? g_q : (z == 1) ? g_k : g_v;

    extern __shared__ float smf[];
    const uint32_t smb = (uint32_t)__cvta_generic_to_shared(smf);

    const int tid = threadIdx.x, wid = tid >> 5, lane = tid & 31;
    const int gid = lane >> 2, tig = lane & 3;
    const int m0 = blockIdx.y * 128, n0 = blockIdx.x * 64;
    const int wm = (wid >> 1) * 64, wn = (wid & 1) * 32;

    float acc[4][4][4] = {};

    #define XS(s,r,c) smf[(s)*4608 + (r)*36 + (c)]
    #define WS(s,r,c) smf[9216 + (s)*2304 + (r)*36 + (c)]   // [n][k]
    auto load_chunk = [&](int s, int k0) {
        #pragma unroll
        for (int t = 0; t < 8; t++) {
            int idx = tid + t * 128, r = idx >> 3, g = idx & 7;
            cp16(smb + (uint32_t)((s * 4608 + r * 36 + g * 4) * 4),
                 X + (size_t)(m0 + r) * DD + k0 + g * 4);
        }
        #pragma unroll
        for (int t = 0; t < 4; t++) {
            int idx = tid + t * 128, r = idx >> 3, g = idx & 7;
            cp16(smb + (uint32_t)((9216 + s * 2304 + r * 36 + g * 4) * 4),
                 W + (size_t)(n0 + r) * DD + k0 + g * 4);
        }
        cp_commit();
    };

    load_chunk(0, 0);
    for (int it = 0; it < 24; it++) {
        if (it + 1 < 24) { load_chunk((it + 1) & 1, (it + 1) * 32); cp_wait<1>(); }
        else cp_wait<0>();
        __syncthreads();
        const int s = it & 1;
        #pragma unroll
        for (int kk = 0; kk < 32; kk += 8) {
            uint32_t a[4][4], b[4][2];
            #pragma unroll
            for (int mi = 0; mi < 4; mi++) {
                int r = wm + mi * 16 + gid;
                uint2 la = *reinterpret_cast<const uint2*>(&XS(s, r, kk + 2 * tig));
                uint2 lb = *reinterpret_cast<const uint2*>(&XS(s, r + 8, kk + 2 * tig));
                a[mi][0] = la.x; a[mi][1] = lb.x; a[mi][2] = la.y; a[mi][3] = lb.y;
            }
            #pragma unroll
            for (int nj = 0; nj < 4; nj++) {
                int n = wn + nj * 8 + gid;
                uint2 w2 = *reinterpret_cast<const uint2*>(&WS(s, n, kk + 2 * tig));
                b[nj][0] = w2.x; b[nj][1] = w2.y;
            }
            #pragma unroll
            for (int mi = 0; mi < 4; mi++)
                #pragma unroll
                for (int nj = 0; nj < 4; nj++) mma8(acc[mi][nj], a[mi], b[nj]);
        }
        __syncthreads();
    }
    #undef XS
    #undef WS

    #pragma unroll
    for (int mi = 0; mi < 4; mi++)
        #pragma unroll
        for (int rr = 0; rr < 2; rr++) {
            int r = m0 + wm + mi * 16 + gid + rr * 8;
            int b_ = r >> 11, sidx = r & 2047;
            #pragma unroll
            for (int nj = 0; nj < 4; nj++) {
                int c = n0 + wn + nj * 8 + tig * 2;
                float v0 = rnd(acc[mi][nj][rr * 2 + 0] + bias[c]);
                float v1 = rnd(acc[mi][nj][rr * 2 + 1] + bias[c + 1]);
                int h = c >> 6, d = c & 63;
                float* o = Y + (((size_t)b_ * HH + h) * SS + sidx) * DKK;
                if (z == 2) {
                    *reinterpret_cast<float2*>(o + d) = make_float2(v0, v1);
                } else {
                    o[PHYS8(d)] = v0;
                    o[PHYS8(d + 1)] = v1;
                }
            }
        }
}

// ---------------------------------------------------------------------------
// Scores+exp: unchanged from R12.
// ---------------------------------------------------------------------------
__global__ void __launch_bounds__(256) scores_kernel(float* __restrict__ attn_ext)
{
    float* attn = attn_ext ? attn_ext : g_attn_fb;
    extern __shared__ uint32_t smu[];
    uint32_t (*Qs)[68] = reinterpret_cast<uint32_t(*)[68]>(smu);
    uint32_t (*Ks)[68] = reinterpret_cast<uint32_t(*)[68]>(smu + 128 * 68);
    float (*Ss)[132]   = reinterpret_cast<float(*)[132]>(smu);

    const int bh = blockIdx.z, b_ = bh / HH;
    const int q0 = blockIdx.y * 128, k0 = blockIdx.x * 128;
    const int tid = threadIdx.x, wid = tid >> 5, lane = tid & 31;
    const int gid = lane >> 2, tig = lane & 3;
    const int wm = (wid >> 1) * 32, wn = (wid & 1) * 64;

    const float* qp = g_q + ((size_t)bh * SS + q0) * DKK;
    const float* kp = g_k + ((size_t)bh * SS + k0) * DKK;

    #pragma unroll
    for (int t = 0; t < 8; t++) {
        int e = (tid + t * 256) * 4, r = e >> 6, c = e & 63;
        *reinterpret_cast<uint4*>(&Qs[r][c]) =
            *reinterpret_cast<const uint4*>(qp + (size_t)r * DKK + c);
        *reinterpret_cast<uint4*>(&Ks[r][c]) =
            *reinterpret_cast<const uint4*>(kp + (size_t)r * DKK + c);
    }
    __syncthreads();

    float acc[2][8][4] = {};
    #pragma unroll
    for (int kk = 0; kk < 64; kk += 8) {
        uint32_t a[2][4], b[8][2];
        #pragma unroll
        for (int mi = 0; mi < 2; mi++) {
            int r = wm + mi * 16 + gid;
            uint2 la = *reinterpret_cast<const uint2*>(&Qs[r][kk + 2 * tig]);
            uint2 lb = *reinterpret_cast<const uint2*>(&Qs[r + 8][kk + 2 * tig]);
            a[mi][0] = la.x; a[mi][1] = lb.x; a[mi][2] = la.y; a[mi][3] = lb.y;
        }
        #pragma unroll
        for (int nj = 0; nj < 8; nj++) {
            int n = wn + nj * 8 + gid;
            uint2 kb = *reinterpret_cast<const uint2*>(&Ks[n][kk + 2 * tig]);
            b[nj][0] = kb.x; b[nj][1] = kb.y;
        }
        #pragma unroll
        for (int mi = 0; mi < 2; mi++)
            #pragma unroll
            for (int nj = 0; nj < 8; nj++) mma8(acc[mi][nj], a[mi], b[nj]);
    }
    __syncthreads();

    #pragma unroll
    for (int mi = 0; mi < 2; mi++)
        #pragma unroll
        for (int rr = 0; rr < 2; rr++) {
            int qrl = wm + mi * 16 + gid + rr * 8;
            int qr = q0 + qrl;
            uint2 mw = *reinterpret_cast<const uint2*>(
                g_maskbits + ((size_t)b_ * SS + qr) * (SS / 32) + (k0 + wn) / 32);
            ull m64 = (ull)mw.x | ((ull)mw.y << 32);
            float rs = 0.f;
            #pragma unroll
            for (int nj = 0; nj < 8; nj++) {
                int j = nj * 8 + tig * 2;
                float v0 = acc[mi][nj][rr * 2 + 0] * 0.125f;
                float v1 = acc[mi][nj][rr * 2 + 1] * 0.125f;
                float p0 = ((m64 >> j) & 1ull) ? 0.f : __expf(v0);
                float p1 = ((m64 >> (j + 1)) & 1ull) ? 0.f : __expf(v1);
                rs += p0 + p1;
                *reinterpret_cast<float2*>(&Ss[qrl][wn + j]) = make_float2(p0, p1);
            }
            rs += __shfl_xor_sync(~0u, rs, 1);
            rs += __shfl_xor_sync(~0u, rs, 2);
            if (tig == 0)
                g_psum[((size_t)bh * SS + qr) * 32 + blockIdx.x * 2 + (wid & 1)] = rs;
        }
    __syncthreads();

    const size_t base = (size_t)bh * SS * SS;
    #pragma unroll
    for (int t = 0; t < 16; t++) {
        int idx = tid + t * 256;
        int r = idx >> 5, c4 = (idx & 31) * 4;
        float4 v = *reinterpret_cast<const float4*>(&Ss[r][c4]);
        *reinterpret_cast<float4*>(attn + base + (size_t)(q0 + r) * SS + k0 + c4) = v;
    }
}

// ---------------------------------------------------------------------------
__global__ void __launch_bounds__(256) rowinv_kernel()
{
    size_t idx = (size_t)blockIdx.x * 256 + threadIdx.x;
    const float4* p = reinterpret_cast<const float4*>(g_psum + idx * 32);
    float s = 0.f;
    #pragma unroll
    for (int t = 0; t < 8; t++) { float4 v = p[t]; s += v.x + v.y + v.z + v.w; }
    g_rowinv[idx] = 1.0f / s;
}

// ---------------------------------------------------------------------------
// Context: unchanged from R12 (near BW floor).
// ---------------------------------------------------------------------------
__global__ void __launch_bounds__(128) context_kernel(float* __restrict__ attn_ext)
{
    float* attn = attn_ext ? attn_ext : g_attn_fb;
    extern __shared__ float smf[];
    const uint32_t smb = (uint32_t)__cvta_generic_to_shared(smf);
    float* invs = smf + 26112;

    const int bh = blockIdx.y, q0 = blockIdx.x * 128;
    const int tid = threadIdx.x, wid = tid >> 5, lane = tid & 31;
    const int gid = lane >> 2, tig = lane & 3;
    const int wm = (wid >> 1) * 64, wn = (wid & 1) * 32;

    float* ap = attn + ((size_t)bh * SS + q0) * SS;
    const float* vp = g_v + (size_t)bh * SS * DKK;

    invs[tid] = g_rowinv[(size_t)bh * SS + q0 + tid];

    #define AS(s,r,c) smf[(s)*8704 + (r)*68 + (c)]
    #define VS(s,r,c) smf[17408 + (s)*4352 + (r)*68 + (c)]
    auto load_chunk = [&](int s, int k0) {
        #pragma unroll
        for (int t = 0; t < 16; t++) {
            int e = (tid + t * 128) * 4, r = e >> 6, c = e & 63;
            cp16(smb + (uint32_t)((s * 8704 + r * 68 + c) * 4),
                 ap + (size_t)r * SS + k0 + c);
        }
        #pragma unroll
        for (int t = 0; t < 8; t++) {
            int e = (tid + t * 128) * 4, r = e >> 6, c = e & 63;
            cp16(smb + (uint32_t)((17408 + s * 4352 + r * 68 + c) * 4),
                 vp + (size_t)(k0 + r) * DKK + c);
        }
        cp_commit();
    };

    float acc[4][4][4] = {};
    load_chunk(0, 0);
    for (int it = 0; it < 32; it++) {
        if (it + 1 < 32) { load_chunk((it + 1) & 1, (it + 1) * 64); cp_wait<1>(); }
        else cp_wait<0>();
        __syncthreads();
        const int s = it & 1;
        const int k0 = it * 64;

        // normalize + global writeback + tf32-cvt in place (attn only)
        #pragma unroll
        for (int t = 0; t < 16; t++) {
            int e = (tid + t * 128) * 4, r = e >> 6, c = e & 63;
            float4 v = *reinterpret_cast<const float4*>(&AS(s, r, c));
            float inv = invs[r];
            v.x *= inv; v.y *= inv; v.z *= inv; v.w *= inv;
            *reinterpret_cast<float4*>(ap + (size_t)r * SS + k0 + c) = v;
            uint32_t* u = reinterpret_cast<uint32_t*>(&AS(s, r, c));
            u[0] = cvt_tf32(v.x); u[1] = cvt_tf32(v.y);
            u[2] = cvt_tf32(v.z); u[3] = cvt_tf32(v.w);
        }
        __syncthreads();

        #pragma unroll
        for (int kk = 0; kk < 64; kk += 8) {
            uint32_t a[4][4], b[4][2];
            #pragma unroll
            for (int mi = 0; mi < 4; mi++) {
                int r = wm + mi * 16 + gid;
                a[mi][0] = __float_as_uint(AS(s, r, kk + tig));
                a[mi][1] = __float_as_uint(AS(s, r + 8, kk + tig));
                a[mi][2] = __float_as_uint(AS(s, r, kk + tig + 4));
                a[mi][3] = __float_as_uint(AS(s, r + 8, kk + tig + 4));
            }
            #pragma unroll
            for (int nj = 0; nj < 4; nj++) {
                int n = wn + nj * 8 + gid;
                b[nj][0] = __float_as_uint(VS(s, kk + tig, n));
                b[nj][1] = __float_as_uint(VS(s, kk + tig + 4, n));
            }
            #pragma unroll
            for (int mi = 0; mi < 4; mi++)
                #pragma unroll
                for (int nj = 0; nj < 4; nj++) mma8(acc[mi][nj], a[mi], b[nj]);
        }
        __syncthreads();
    }
    #undef AS
    #undef VS

    const int b_ = bh / HH, h = bh % HH;
    #pragma unroll
    for (int mi = 0; mi < 4; mi++)
        #pragma unroll
        for (int rr = 0; rr < 2; rr++) {
            int s = q0 + wm + mi * 16 + gid + rr * 8;
            #pragma unroll
            for (int nj = 0; nj < 4; nj++) {
                int d = wn + nj * 8 + tig * 2;
                float r0 = rnd(acc[mi][nj][rr * 2]);
                float r1 = rnd(acc[mi][nj][rr * 2 + 1]);
                float* o = &g_ctx[((size_t)b_ * SS + s) * DD + h * DKK];
                o[PHYS8(d)] = r0;
                o[PHYS8(d + 1)] = r1;
            }
        }
}

// ---------------------------------------------------------------------------
// Output projection: BK=32, 2-stage, 3 CTAs/SM. Warp tile 64x32.
// ---------------------------------------------------------------------------
__global__ void __launch_bounds__(128, 3) outproj_kernel(
    const float* __restrict__ bias, const float* __restrict__ resid)
{
    const float* X = g_ctx;
    const float* W = g_wTp[3];
    extern __shared__ float smf[];
    const uint32_t smb = (uint32_t)__cvta_generic_to_shared(smf);

    const int tid = threadIdx.x, wid = tid >> 5, lane = tid & 31;
    const int gid = lane >> 2, tig = lane & 3;
    const int m0 = blockIdx.y * 128, n0 = blockIdx.x * 64;
    const int wm = (wid >> 1) * 64, wn = (wid & 1) * 32;

    float acc[4][4][4] = {};

    #define XS(s,r,c) smf[(s)*4608 + (r)*36 + (c)]
    #define WS(s,r,c) smf[9216 + (s)*2304 + (r)*36 + (c)]
    auto load_chunk = [&](int s, int k0) {
        #pragma unroll
        for (int t = 0; t < 8; t++) {
            int idx = tid + t * 128, r = idx >> 3, g = idx & 7;
            cp16(smb + (uint32_t)((s * 4608 + r * 36 + g * 4) * 4),
                 X + (size_t)(m0 + r) * DD + k0 + g * 4);
        }
        #pragma unroll
        for (int t = 0; t < 4; t++) {
            int idx = tid + t * 128, r = idx >> 3, g = idx & 7;
            cp16(smb + (uint32_t)((9216 + s * 2304 + r * 36 + g * 4) * 4),
                 W + (size_t)(n0 + r) * DD + k0 + g * 4);
        }
        cp_commit();
    };

    load_chunk(0, 0);
    for (int it = 0; it < 24; it++) {
        if (it + 1 < 24) { load_chunk((it + 1) & 1, (it + 1) * 32); cp_wait<1>(); }
        else cp_wait<0>();
        __syncthreads();
        const int s = it & 1;
        #pragma unroll
        for (int kk = 0; kk < 32; kk += 8) {
            uint32_t a[4][4], b[4][2];
            #pragma unroll
            for (int mi = 0; mi < 4; mi++) {
                int r = wm + mi * 16 + gid;
                uint2 la = *reinterpret_cast<const uint2*>(&XS(s, r, kk + 2 * tig));
                uint2 lb = *reinterpret_cast<const uint2*>(&XS(s, r + 8, kk + 2 * tig));
                a[mi][0] = la.x; a[mi][1] = lb.x; a[mi][2] = la.y; a[mi][3] = lb.y;
            }
            #pragma unroll
            for (int nj = 0; nj < 4; nj++) {
                int n = wn + nj * 8 + gid;
                uint2 w2 = *reinterpret_cast<const uint2*>(&WS(s, n, kk + 2 * tig));
                b[nj][0] = w2.x; b[nj][1] = w2.y;
            }
            #pragma unroll
            for (int mi = 0; mi < 4; mi++)
                #pragma unroll
                for (int nj = 0; nj < 4; nj++) mma8(acc[mi][nj], a[mi], b[nj]);
        }
        __syncthreads();
    }
    #undef XS
    #undef WS

    #pragma unroll
    for (int mi = 0; mi < 4; mi++)
        #pragma unroll
        for (int rr = 0; rr < 2; rr++) {
            int r = m0 + wm + mi * 16 + gid + rr * 8;
            #pragma unroll
            for (int nj = 0; nj < 4; nj++) {
                int c = n0 + wn + nj * 8 + tig * 2;
                float v0 = acc[mi][nj][rr * 2 + 0] + bias[c];
                float v1 = acc[mi][nj][rr * 2 + 1] + bias[c + 1];
                const float2 rs = *reinterpret_cast<const float2*>(&resid[(size_t)r * DD + c]);
                *reinterpret_cast<float2*>(&g_pre[(size_t)r * DD + c]) =
                    make_float2(v0 + rs.x, v1 + rs.y);
            }
        }
}

// ---------------------------------------------------------------------------
// LayerNorm over D=768.
// ---------------------------------------------------------------------------
__global__ void __launch_bounds__(256) ln_kernel(
    const float* __restrict__ lg, const float* __restrict__ lb, float* __restrict__ out)
{
    const size_t row = blockIdx.x;
    const float* x = g_pre + row * DD;
    const int tid = threadIdx.x;
    __shared__ float red[8];

    float v[3];
    float s = 0.f;
    #pragma unroll
    for (int t = 0; t < 3; t++) { v[t] = x[tid + t * 256]; s += v[t]; }
    #pragma unroll
    for (int o = 16; o; o >>= 1) s += __shfl_xor_sync(~0u, s, o);
    if ((tid & 31) == 0) red[tid >> 5] = s;
    __syncthreads();
    s = 0.f;
    #pragma unroll
    for (int w = 0; w < 8; w++) s += red[w];
    const float mu = s * (1.0f / DD);
    __syncthreads();

    float var = 0.f;
    #pragma unroll
    for (int t = 0; t < 3; t++) { float d = v[t] - mu; var += d * d; }
    #pragma unroll
    for (int o = 16; o; o >>= 1) var += __shfl_xor_sync(~0u, var, o);
    if ((tid & 31) == 0) red[tid >> 5] = var;
    __syncthreads();
    var = 0.f;
    #pragma unroll
    for (int w = 0; w < 8; w++) var += red[w];
    const float inv = rsqrtf(var * (1.0f / DD) + 1e-5f);

    #pragma unroll
    for (int t = 0; t < 3; t++) {
        int c = tid + t * 256;
        out[row * DD + c] = (v[t] - mu) * inv * lg[c] + lb[c];
    }
}

// ---------------------------------------------------------------------------
extern "C" void kernel_launch(void* const* d_in, const int* in_sizes, int n_in,
                              void* d_out, int out_size)
{
    const float* Q  = (const float*)d_in[0];
    const float* K  = (const float*)d_in[1];
    const float* V  = (const float*)d_in[2];
    const int*   pad = (const int*)d_in[3];
    const float* Wq = (const float*)d_in[4];
    const float* bq = (const float*)d_in[5];
    const float* Wk = (const float*)d_in[6];
    const float* bk = (const float*)d_in[7];
    const float* Wv = (const float*)d_in[8];
    const float* bv = (const float*)d_in[9];
    const float* Wo = (const float*)d_in[10];
    const float* bo = (const float*)d_in[11];
    const float* lg = (const float*)d_in[12];
    const float* lb = (const float*)d_in[13];
    float* out = (float*)d_out;

    float* attn = ((long long)out_size >= OUT_ELEMS + ATTN_ELEMS) ? (out + OUT_ELEMS)
                                                                  : nullptr;

    const int GEMM_SMEM   = 13824 * 4;   // 55296
    const int SCORES_SMEM = 17408 * 4;   // 69632
    const int CTX_SMEM    = 26240 * 4;   // 104960
    cudaFuncSetAttribute(qkv_kernel, cudaFuncAttributeMaxDynamicSharedMemorySize, GEMM_SMEM);
    cudaFuncSetAttribute(outproj_kernel, cudaFuncAttributeMaxDynamicSharedMemorySize, GEMM_SMEM);
    cudaFuncSetAttribute(scores_kernel, cudaFuncAttributeMaxDynamicSharedMemorySize, SCORES_SMEM);
    cudaFuncSetAttribute(context_kernel, cudaFuncAttributeMaxDynamicSharedMemorySize, CTX_SMEM);

    maskpack_kernel<<<(BB * SS * (SS / 32)) / 256, 256>>>(pad);
    wtrans_kernel<<<dim3(24, 24, 4), 256>>>(Wq, Wk, Wv, Wo);
    roundperm_kernel<<<dim3((BB * SS * DD / 8) / 256, 3), 256>>>(Q, K, V);

    dim3 gq(DD / 64, (BB * SS) / 128, 3);       // (12, 64, 3)
    qkv_kernel<<<gq, 128, GEMM_SMEM>>>(bq, bk, bv);

    dim3 gs(SS / 128, SS / 128, BB * HH);       // (16, 16, 48)
    scores_kernel<<<gs, 256, SCORES_SMEM>>>(attn);

    rowinv_kernel<<<(BB * HH * SS) / 256, 256>>>();

    dim3 gc(SS / 128, BB * HH);                 // (16, 48)
    context_kernel<<<gc, 128, CTX_SMEM>>>(attn);

    dim3 gp(DD / 64, (BB * SS) / 128);          // (12, 64)
    outproj_kernel<<<gp, 128, GEMM_SMEM>>>(bo, Q);

    ln_kernel<<<BB * SS, 256>>>(lg, lb, out);
}